// round 10
// baseline (speedup 1.0000x reference)
#include <cuda_runtime.h>
#include <cuda_bf16.h>
#include <math.h>
#include <stdint.h>

#define BATCH 16
#define TLEN  2048
#define MTOT  (BATCH * TLEN)
#define LRELU_SLOPE 0.02f
#define GN_EPS 1e-5

typedef unsigned long long u64;
typedef unsigned int u32;
typedef unsigned short u16;

// ---------------- scratch ----------------
__device__ float g_bufA[(size_t)MTOT * 1024];     // enc [B][C][T] then dec [m][1024]
__device__ float g_bufB[(size_t)MTOT * 512];
__device__ float g_z   [(size_t)MTOT * 128];      // [B][128][T]
__device__ float g_spkn[64 * 128];
__device__ float g_cbn [512 * 128];
__device__ u16   g_catH[(size_t)MTOT * 640], g_catM[(size_t)MTOT * 640], g_catL[(size_t)MTOT * 640];
// encoder weights fp32 [CI][K][CO]
__device__ float g_we0[39 * 5 * 1024];
__device__ float g_we1[1024 * 5 * 512];
__device__ float g_we2[512 * 5 * 512];
__device__ float g_wm [512 * 128];
// decoder weights split3 [co][k*CS+ci]
__device__ u16 g_d0h[1024 * 1280], g_d0m[1024 * 1280], g_d0l[1024 * 1280];
__device__ u16 g_d1h[1024 * 3200], g_d1m[1024 * 3200], g_d1l[1024 * 3200];
__device__ u16 g_d2h[39 * 3200],   g_d2m[39 * 3200],   g_d2l[39 * 3200];
__device__ double g_stats[2 * BATCH];

// ---------------- common helpers ----------------
__device__ __forceinline__ u64 ffma2(u64 a, u64 b, u64 c) {
    u64 d; asm("fma.rn.f32x2 %0, %1, %2, %3;" : "=l"(d) : "l"(a), "l"(b), "l"(c));
    return d;
}
__device__ __forceinline__ float2 unpack2(u64 v) {
    float2 f; asm("mov.b64 {%0, %1}, %2;" : "=f"(f.x), "=f"(f.y) : "l"(v));
    return f;
}
__device__ __forceinline__ void cp_async4(void* smem, const float* g, bool p) {
    unsigned s = (unsigned)__cvta_generic_to_shared(smem);
    int sz = p ? 4 : 0;
    asm volatile("cp.async.ca.shared.global [%0], [%1], 4, %2;"
                 :: "r"(s), "l"(g), "r"(sz));
}
__device__ __forceinline__ u32 smem_u32(const void* p) {
    u32 a;
    asm("{ .reg .u64 t; cvta.to.shared.u64 t, %1; cvt.u32.u64 %0, t; }"
        : "=r"(a) : "l"(p));
    return a;
}
__device__ __forceinline__ void cp_async16(u32 saddr, const void* g, bool p) {
    int sz = p ? 16 : 0;
    asm volatile("cp.async.cg.shared.global [%0], [%1], 16, %2;"
                 :: "r"(saddr), "l"(g), "r"(sz));
}
#define CP_COMMIT() asm volatile("cp.async.commit_group;" ::: "memory")
#define CP_WAIT(n)  asm volatile("cp.async.wait_group %0;" :: "n"(n) : "memory")
#define SW128(o) ((u32)(o) ^ ((((u32)(o)) >> 3) & 0x70u))

__device__ __forceinline__ void ldsm4(u32* r, u32 addr) {
    asm volatile("ldmatrix.sync.aligned.m8n8.x4.shared.b16 {%0,%1,%2,%3}, [%4];"
                 : "=r"(r[0]), "=r"(r[1]), "=r"(r[2]), "=r"(r[3]) : "r"(addr));
}
__device__ __forceinline__ void mma_bf16(float* d, const u32* a, const u32* b) {
    asm volatile(
        "mma.sync.aligned.m16n8k16.row.col.f32.bf16.bf16.f32 "
        "{%0,%1,%2,%3},{%4,%5,%6,%7},{%8,%9},{%0,%1,%2,%3};"
        : "+f"(d[0]), "+f"(d[1]), "+f"(d[2]), "+f"(d[3])
        : "r"(a[0]), "r"(a[1]), "r"(a[2]), "r"(a[3]), "r"(b[0]), "r"(b[1]));
}
__device__ __forceinline__ void split3(float v, u16* H, u16* M, u16* L, size_t i) {
    __nv_bfloat16 h = __float2bfloat16(v);
    float r1 = v - __bfloat162float(h);
    __nv_bfloat16 m = __float2bfloat16(r1);
    float r2 = r1 - __bfloat162float(m);
    __nv_bfloat16 l = __float2bfloat16(r2);
    H[i] = *(u16*)&h; M[i] = *(u16*)&m; L[i] = *(u16*)&l;
}

// ---------------- prep kernels ----------------
__global__ void normalize_rows_kernel(const float* __restrict__ in,
                                      float* __restrict__ out) {
    int r = blockIdx.x, tid = threadIdx.x;
    float v = in[r * 128 + tid];
    __shared__ float sh[128];
    sh[tid] = v * v;
    __syncthreads();
    for (int off = 64; off > 0; off >>= 1) {
        if (tid < off) sh[tid] += sh[tid + off];
        __syncthreads();
    }
    out[r * 128 + tid] = v * rsqrtf(sh[0] + 1e-12f);
}

// encoder Conv1d weight [CO][CI][K] -> [CI][K][CO] fp32
__global__ void wenc_kernel(const float* __restrict__ W, float* __restrict__ Wp,
                            int CI, int CO, int K) {
    int idx = blockIdx.x * 256 + threadIdx.x;
    if (idx >= CO * CI * K) return;
    int k  = idx % K;
    int ci = (idx / K) % CI;
    int co = idx / (K * CI);
    Wp[((size_t)ci * K + k) * CO + co] = W[idx];
}

// decoder ConvTranspose [CIo][CO][5] -> split3 [co][k*CS+ci] (flip + cat remap)
__global__ void wsplit_dec(const float* __restrict__ W, u16* Wh, u16* Wm, u16* Wl,
                           int CS, int CO, int split) {
    int i = blockIdx.x * 256 + threadIdx.x;
    if (i >= CO * 5 * CS) return;
    int co = i / (5 * CS), j = i % (5 * CS);
    int k = j / CS, ci = j % CS;
    int ci0 = (ci < 128) ? ci + split : ci - 128;
    float v = W[((size_t)ci0 * CO + co) * 5 + (4 - k)];
    split3(v, Wh, Wm, Wl, i);
}

__global__ void gather_yv_kernel(const int* __restrict__ y,
                                 const float* __restrict__ spkn,
                                 u16* __restrict__ H, u16* __restrict__ M,
                                 u16* __restrict__ L) {
    int m = blockIdx.x;
    int idx = y[m];
    split3(spkn[idx * 128 + threadIdx.x], H, M, L, (size_t)m * 640 + threadIdx.x);
}

__global__ void zero_stats_kernel() {
    if (threadIdx.x < 2 * BATCH) g_stats[threadIdx.x] = 0.0;
}

// ================= R3 encoder conv (FFMA2, [B][C][T]) — verbatim =========
template <int K>
__device__ __forceinline__ void stage_tiles(
    const float* __restrict__ Xb, const float* __restrict__ Wp,
    float* XsBuf, float* WsBuf, int cb, int CI, int CO, int t0, int o0, int tid) {
    const int BM = 128, XR = 128 + (K - 1), PAD = (K - 1) / 2;
    for (int i = tid; i < 8 * XR; i += 256) {
        int ci = i / XR, t = i % XR;
        int gci = cb + ci, gt = t0 + t - PAD;
        bool p = (gci < CI) && ((unsigned)gt < (unsigned)TLEN);
        const float* src = p ? (Xb + (size_t)gci * TLEN + gt) : Xb;
        cp_async4(XsBuf + ci * XR + t, src, p);
    }
    for (int i = tid; i < 8 * K * BM; i += 256) {
        int ci = i / (K * BM);
        int r  = i % (K * BM);
        int k = r / BM, o = r % BM;
        int gci = cb + ci, go = o0 + o;
        bool p = (gci < CI) && (go < CO);
        const float* src = p ? (Wp + ((size_t)gci * K + k) * CO + go) : Wp;
        cp_async4(WsBuf + i, src, p);
    }
}

template <int K>
__global__ void __launch_bounds__(256, 2)
conv_f2_kernel(const float* __restrict__ X, const float* __restrict__ Wp,
               const float* __restrict__ bias, float* __restrict__ Y,
               int CI, int CBx, int CO, int doStats) {
    const int BM = 128, BN = 128, BK = 8;
    const int XR = BN + (K - 1);
    const int NX = 8 + K - 1;
    const int XSZ = BK * XR;
    const int WSZ = BK * K * BM;

    extern __shared__ float sm[];
    float* Xs0 = sm;
    float* Ws0 = sm + 2 * XSZ;
    float* red = Ws0 + 2 * WSZ;

    int b  = blockIdx.z;
    int t0 = blockIdx.x * BN;
    int o0 = blockIdx.y * BM;
    int tid = threadIdx.x;
    int warp = tid >> 5, lane = tid & 31;
    int wco = warp & 1, wt = warp >> 1;
    int lco = lane >> 2, lt = lane & 3;
    int tco = wco * 64 + lco * 8;
    int tt  = wt * 32 + lt * 8;

    const float* Xb = X + (size_t)b * CBx * TLEN;
    int nchunk = (CI + BK - 1) / BK;

    u64 acc[4][8];
#pragma unroll
    for (int p = 0; p < 4; p++)
#pragma unroll
        for (int j = 0; j < 8; j++) acc[p][j] = 0ull;

    stage_tiles<K>(Xb, Wp, Xs0, Ws0, 0, CI, CO, t0, o0, tid);
    CP_COMMIT();

    for (int c = 0; c < nchunk; c++) {
        int buf = c & 1;
        if (c + 1 < nchunk) {
            stage_tiles<K>(Xb, Wp, Xs0 + (buf ^ 1) * XSZ, Ws0 + (buf ^ 1) * WSZ,
                           (c + 1) * BK, CI, CO, t0, o0, tid);
            CP_COMMIT();
            CP_WAIT(1);
        } else {
            CP_WAIT(0);
        }
        __syncthreads();

        const float* Xsb = Xs0 + buf * XSZ;
        const float* Wsb = Ws0 + buf * WSZ;
#pragma unroll
        for (int ci = 0; ci < BK; ci++) {
            u64 xs[NX];
#pragma unroll
            for (int v4 = 0; v4 < (NX + 3) / 4; v4++) {
                float4 xv = *(const float4*)&Xsb[ci * XR + tt + v4 * 4];
                if (v4 * 4 + 0 < NX) { u64 r; asm("mov.b64 %0,{%1,%1};":"=l"(r):"f"(xv.x)); xs[v4*4+0]=r; }
                if (v4 * 4 + 1 < NX) { u64 r; asm("mov.b64 %0,{%1,%1};":"=l"(r):"f"(xv.y)); xs[v4*4+1]=r; }
                if (v4 * 4 + 2 < NX) { u64 r; asm("mov.b64 %0,{%1,%1};":"=l"(r):"f"(xv.z)); xs[v4*4+2]=r; }
                if (v4 * 4 + 3 < NX) { u64 r; asm("mov.b64 %0,{%1,%1};":"=l"(r):"f"(xv.w)); xs[v4*4+3]=r; }
            }
#pragma unroll
            for (int k = 0; k < K; k++) {
                const float* wrow = Wsb + (ci * K + k) * BM + tco;
                ulonglong2 wa = *(const ulonglong2*)(wrow);
                ulonglong2 wb = *(const ulonglong2*)(wrow + 4);
                u64 wp[4] = {wa.x, wa.y, wb.x, wb.y};
#pragma unroll
                for (int p = 0; p < 4; p++)
#pragma unroll
                    for (int j = 0; j < 8; j++)
                        acc[p][j] = ffma2(wp[p], xs[j + k], acc[p][j]);
            }
        }
        __syncthreads();
    }

    int gt = t0 + tt;
    float ssum = 0.f, ssq = 0.f;
#pragma unroll
    for (int p = 0; p < 4; p++) {
        int oa = o0 + tco + 2 * p;
        int ob = oa + 1;
        bool va = oa < CO, vb = ob < CO;
        float ba = va ? bias[oa] : 0.f;
        float bb = vb ? bias[ob] : 0.f;
        float fa[8], fb[8];
#pragma unroll
        for (int j = 0; j < 8; j++) {
            float2 v = unpack2(acc[p][j]);
            fa[j] = v.x + ba; fb[j] = v.y + bb;
            if (va) { ssum += fa[j]; ssq += fa[j] * fa[j]; }
            if (vb) { ssum += fb[j]; ssq += fb[j] * fb[j]; }
        }
        if (va) {
            float* rowa = Y + ((size_t)b * CO + oa) * TLEN + gt;
            *(float4*)(rowa)     = make_float4(fa[0], fa[1], fa[2], fa[3]);
            *(float4*)(rowa + 4) = make_float4(fa[4], fa[5], fa[6], fa[7]);
        }
        if (vb) {
            float* rowb = Y + ((size_t)b * CO + ob) * TLEN + gt;
            *(float4*)(rowb)     = make_float4(fb[0], fb[1], fb[2], fb[3]);
            *(float4*)(rowb + 4) = make_float4(fb[4], fb[5], fb[6], fb[7]);
        }
    }
    if (doStats) {
#pragma unroll
        for (int off = 16; off > 0; off >>= 1) {
            ssum += __shfl_down_sync(0xffffffffu, ssum, off);
            ssq  += __shfl_down_sync(0xffffffffu, ssq,  off);
        }
        if (lane == 0) { red[warp] = ssum; red[8 + warp] = ssq; }
        __syncthreads();
        if (tid == 0) {
            double s = 0.0, s2 = 0.0;
            for (int w = 0; w < 8; w++) { s += red[w]; s2 += red[8 + w]; }
            atomicAdd(&g_stats[2 * b],     s);
            atomicAdd(&g_stats[2 * b + 1], s2);
        }
    }
}

__global__ void gn_lrelu_kernel(float* __restrict__ X,
                                const float* __restrict__ g,
                                const float* __restrict__ bt, int C) {
    int b = blockIdx.z, c = blockIdx.y;
    int t = blockIdx.x * 256 + threadIdx.x;
    double N = (double)C * TLEN;
    double mean = g_stats[2 * b] / N;
    double var  = g_stats[2 * b + 1] / N - mean * mean;
    float rstd = (float)rsqrt(var + GN_EPS);
    float sc = g[c] * rstd;
    float sh = bt[c] - (float)mean * sc;
    size_t idx = ((size_t)b * C + c) * TLEN + t;
    float yv = X[idx] * sc + sh;
    X[idx] = yv >= 0.f ? yv : LRELU_SLOPE * yv;
}

// VQ on [B][128][T] z (R3-proven argmax); emits split3 zq into cat[m][128..255]
__global__ void vq_kernel(const float* __restrict__ z,
                          const float* __restrict__ cbn,
                          u16* __restrict__ catH, u16* __restrict__ catM,
                          u16* __restrict__ catL) {
    __shared__ float zs[8][128];
    int warp = threadIdx.x >> 5, lane = threadIdx.x & 31;
    int pos = blockIdx.x * 8 + warp;
    int b = pos / TLEN, t = pos % TLEN;

    for (int d = lane; d < 128; d += 32)
        zs[warp][d] = z[((size_t)b * 128 + d) * TLEN + t];
    __syncwarp();

    const float4* zs4 = (const float4*)zs[warp];
    float best = -1e30f;
    int bk = 0;
    for (int kk = 0; kk < 16; kk++) {
        int k = kk * 32 + lane;
        const float4* cb4 = (const float4*)(cbn + (size_t)k * 128);
        float s = 0.f;
#pragma unroll
        for (int d4 = 0; d4 < 32; d4++) {
            float4 zv = zs4[d4], cv = cb4[d4];
            s += zv.x * cv.x + zv.y * cv.y + zv.z * cv.z + zv.w * cv.w;
        }
        if (s > best || (s == best && k < bk)) { best = s; bk = k; }
    }
    for (int off = 16; off > 0; off >>= 1) {
        float ob = __shfl_down_sync(0xffffffff, best, off);
        int   ok = __shfl_down_sync(0xffffffff, bk,   off);
        if (ob > best || (ob == best && ok < bk)) { best = ob; bk = ok; }
    }
    bk = __shfl_sync(0xffffffff, bk, 0);
    for (int d = lane; d < 128; d += 32)
        split3(cbn[(size_t)bk * 128 + d], catH, catM, catL,
               (size_t)pos * 640 + 128 + d);
}

// ================= decoder: split3 mma.sync GEMM =========================
template <int MODE>
__global__ void __launch_bounds__(256)
gemm_mma_kernel(const u16* __restrict__ AH, const u16* __restrict__ AM,
                const u16* __restrict__ AL,
                const u16* __restrict__ WH, const u16* __restrict__ WM,
                const u16* __restrict__ WL,
                const float* __restrict__ bias, float* __restrict__ Y,
                int RS, int CS, int K, int CO, int doStats) {
    const int NA = 3;
    const int BUFB = 2 * NA * 16384;
    extern __shared__ char dsm[];
    __shared__ float s_bias[128];
    __shared__ float s_red[16];

    const int PAD = (K - 1) / 2;
    const int KP = K * CS;
    const int cs64 = CS >> 6;
    const int nch = K * cs64;

    int tid = threadIdx.x, wid = tid >> 5, lane = tid & 31;
    int co0 = blockIdx.x * 128, m0 = blockIdx.y * 128;
    u32 sb = smem_u32(dsm);

    const u16* As[3] = {AH, AM, AL};
    const u16* Ws[3] = {WH, WM, WL};

    auto stage = [&](int c, int buf) {
        int k = c / cs64;
        int cib = (c - k * cs64) << 6;
        int dk = k - PAD;
        u32 base = sb + buf * BUFB;
        for (int i = tid; i < 1024; i += 256) {
            int r = i >> 3, g7 = i & 7;
            u32 soff = SW128(r * 128 + g7 * 16);
            int m = m0 + r;
            int tt = (m & 2047) + dk;
            bool pv = (unsigned)tt < 2048u;
            size_t aoff = (size_t)(m + dk) * RS + cib + g7 * 8;
#pragma unroll
            for (int s = 0; s < NA; s++)
                cp_async16(base + s * 16384 + soff, pv ? As[s] + aoff : As[s], pv);
            int co = co0 + r;
            bool pw = co < CO;
            size_t woff = (size_t)co * KP + c * 64 + g7 * 8;
            u32 wb = base + NA * 16384;
#pragma unroll
            for (int s = 0; s < NA; s++)
                cp_async16(wb + s * 16384 + soff, pw ? Ws[s] + woff : Ws[s], pw);
        }
        CP_COMMIT();
    };

    float acc[2][8][4];
#pragma unroll
    for (int a = 0; a < 2; a++)
#pragma unroll
        for (int b = 0; b < 8; b++)
#pragma unroll
            for (int c = 0; c < 4; c++) acc[a][b][c] = 0.f;

    int wm = (wid & 3) * 32, wn = (wid >> 2) * 64;
    int quad = lane >> 3, l7 = lane & 7;
    int arow = wm + (quad & 1) * 8 + l7;
    int acolb = (quad >> 1) * 16;
    int brow = wn + (quad >> 1) * 8 + l7;
    int bcolb = (quad & 1) * 16;

    const int AP[6] = {0, 0, 1, 0, 1, 2};
    const int BP[6] = {0, 1, 0, 2, 1, 0};

    stage(0, 0);

    for (int c = 0; c < nch; c++) {
        int buf = c & 1;
        if (c + 1 < nch) { stage(c + 1, buf ^ 1); CP_WAIT(1); }
        else             { CP_WAIT(0); }
        __syncthreads();

        u32 baseA = sb + buf * BUFB;
        u32 baseW = baseA + NA * 16384;
#pragma unroll
        for (int ks = 0; ks < 4; ks++) {
            u32 a[3][2][4];
#pragma unroll
            for (int s = 0; s < NA; s++)
#pragma unroll
                for (int mt = 0; mt < 2; mt++) {
                    u32 off = SW128((arow + mt * 16) * 128 + acolb + ks * 32);
                    ldsm4(a[s][mt], baseA + s * 16384 + off);
                }
#pragma unroll
            for (int nt2 = 0; nt2 < 4; nt2++) {
                u32 off = SW128((brow + nt2 * 16) * 128 + bcolb + ks * 32);
                u32 bb[3][4];
#pragma unroll
                for (int s = 0; s < NA; s++)
                    ldsm4(bb[s], baseW + s * 16384 + off);
#pragma unroll
                for (int mt = 0; mt < 2; mt++) {
#pragma unroll
                    for (int p = 0; p < 6; p++) {
                        mma_bf16(acc[mt][2 * nt2],     a[AP[p]][mt], bb[BP[p]]);
                        mma_bf16(acc[mt][2 * nt2 + 1], a[AP[p]][mt], bb[BP[p]] + 2);
                    }
                }
            }
        }
        __syncthreads();
    }

    if (tid < 128) {
        int co = co0 + tid;
        s_bias[tid] = (co < CO) ? bias[co] : 0.f;
    }
    __syncthreads();

    int g = lane >> 2, tg = lane & 3;
    float ssum = 0.f, ssq = 0.f;
#pragma unroll
    for (int mt = 0; mt < 2; mt++) {
#pragma unroll
        for (int nt = 0; nt < 8; nt++) {
            int colb = wn + nt * 8 + tg * 2;
            float b0 = s_bias[colb], b1 = s_bias[colb + 1];
            float f00 = acc[mt][nt][0] + b0, f01 = acc[mt][nt][1] + b1;
            float f10 = acc[mt][nt][2] + b0, f11 = acc[mt][nt][3] + b1;
            int m1 = m0 + wm + mt * 16 + g;
            int co = co0 + colb;
            if (MODE == 0) {
                *(float2*)&Y[(size_t)m1 * CO + co] = make_float2(f00, f01);
                *(float2*)&Y[(size_t)(m1 + 8) * CO + co] = make_float2(f10, f11);
                ssum += f00 + f01 + f10 + f11;
                ssq += f00 * f00 + f01 * f01 + f10 * f10 + f11 * f11;
            } else {
                int b = m1 >> 11, t = m1 & 2047;
                if (co < CO) {
                    Y[((size_t)b * CO + co) * TLEN + t] = f00;
                    Y[((size_t)b * CO + co) * TLEN + t + 8] = f10;
                }
                if (co + 1 < CO) {
                    Y[((size_t)b * CO + co + 1) * TLEN + t] = f01;
                    Y[((size_t)b * CO + co + 1) * TLEN + t + 8] = f11;
                }
            }
        }
    }

    if (MODE == 0 && doStats) {
#pragma unroll
        for (int off = 16; off > 0; off >>= 1) {
            ssum += __shfl_down_sync(0xffffffffu, ssum, off);
            ssq  += __shfl_down_sync(0xffffffffu, ssq,  off);
        }
        if (lane == 0) { s_red[wid] = ssum; s_red[8 + wid] = ssq; }
        __syncthreads();
        if (tid == 0) {
            double s = 0.0, s2 = 0.0;
            for (int w = 0; w < 8; w++) { s += s_red[w]; s2 += s_red[8 + w]; }
            int b = m0 >> 11;
            atomicAdd(&g_stats[2 * b], s);
            atomicAdd(&g_stats[2 * b + 1], s2);
        }
    }
}

__global__ void gn_glu_split3(const float* __restrict__ X,
                              const float* __restrict__ g,
                              const float* __restrict__ bt,
                              u16* __restrict__ catH, u16* __restrict__ catM,
                              u16* __restrict__ catL) {
    int m = blockIdx.y;
    int c = blockIdx.x * 256 + threadIdx.x;  // < 512
    int b = m >> 11;
    double N = 1024.0 * TLEN;
    double mean = g_stats[2 * b] / N;
    double var  = g_stats[2 * b + 1] / N - mean * mean;
    float rstd = (float)rsqrt(var + GN_EPS);
    float mf = (float)mean;
    float a  = X[(size_t)m * 1024 + c];
    float gv = X[(size_t)m * 1024 + 512 + c];
    float na = (a  - mf) * rstd * g[c]       + bt[c];
    float ng = (gv - mf) * rstd * g[c + 512] + bt[c + 512];
    float v = na / (1.f + expf(-ng));
    split3(v, catH, catM, catL, (size_t)m * 640 + 128 + c);
}

// ---------------- host ----------------
static const int SMEM_K5 = (2 * (8 * 132) + 2 * (8 * 5 * 128) + 16) * 4;
static const int SMEM_K1 = (2 * (8 * 128) + 2 * (8 * 1 * 128) + 16) * 4;
static const int SMEM_P6 = 2 * 3 * 2 * 16384;

static void launch_conv(const float* X, const float* Wp, const float* b,
                        float* Y, int CI, int CBx, int CO, int K, int doStats) {
    dim3 grid(TLEN / 128, (CO + 127) / 128, BATCH);
    if (doStats) zero_stats_kernel<<<1, 32>>>();
    if (K == 5)
        conv_f2_kernel<5><<<grid, 256, SMEM_K5>>>(X, Wp, b, Y, CI, CBx, CO, doStats);
    else
        conv_f2_kernel<1><<<grid, 256, SMEM_K1>>>(X, Wp, b, Y, CI, CBx, CO, doStats);
}

extern "C" void kernel_launch(void* const* d_in, const int* in_sizes, int n_in,
                              void* d_out, int out_size) {
    const float* x    = (const float*)d_in[0];
    const int*   y    = (const int*)  d_in[1];
    const float* spk  = (const float*)d_in[2];
    const float* cb   = (const float*)d_in[3];
    const float *ew0 = (const float*)d_in[4],  *eb0 = (const float*)d_in[5];
    const float *eg0 = (const float*)d_in[6],  *et0 = (const float*)d_in[7];
    const float *ew1 = (const float*)d_in[8],  *eb1 = (const float*)d_in[9];
    const float *eg1 = (const float*)d_in[10], *et1 = (const float*)d_in[11];
    const float *ew2 = (const float*)d_in[12], *eb2 = (const float*)d_in[13];
    const float *eg2 = (const float*)d_in[14], *et2 = (const float*)d_in[15];
    const float *mw  = (const float*)d_in[16], *mb  = (const float*)d_in[17];
    const float *dw0 = (const float*)d_in[18], *db0 = (const float*)d_in[19];
    const float *dg0 = (const float*)d_in[20], *dt0 = (const float*)d_in[21];
    const float *dw1 = (const float*)d_in[22], *db1 = (const float*)d_in[23];
    const float *dg1 = (const float*)d_in[24], *dt1 = (const float*)d_in[25];
    const float *dw2 = (const float*)d_in[26], *db2 = (const float*)d_in[27];
    float* out = (float*)d_out;

    cudaFuncSetAttribute(conv_f2_kernel<5>,
                         cudaFuncAttributeMaxDynamicSharedMemorySize, SMEM_K5);
    cudaFuncSetAttribute(conv_f2_kernel<1>,
                         cudaFuncAttributeMaxDynamicSharedMemorySize, SMEM_K1);
    cudaFuncSetAttribute(gemm_mma_kernel<0>,
                         cudaFuncAttributeMaxDynamicSharedMemorySize, SMEM_P6);
    cudaFuncSetAttribute(gemm_mma_kernel<2>,
                         cudaFuncAttributeMaxDynamicSharedMemorySize, SMEM_P6);

    float *bufA, *bufB, *z, *spkn, *cbn, *we0, *we1, *we2, *wm;
    u16 *catH, *catM, *catL;
    u16 *d0h, *d0m, *d0l, *d1h, *d1m, *d1l, *d2h, *d2m, *d2l;
    cudaGetSymbolAddress((void**)&bufA, g_bufA);
    cudaGetSymbolAddress((void**)&bufB, g_bufB);
    cudaGetSymbolAddress((void**)&z,    g_z);
    cudaGetSymbolAddress((void**)&spkn, g_spkn);
    cudaGetSymbolAddress((void**)&cbn,  g_cbn);
    cudaGetSymbolAddress((void**)&we0,  g_we0);
    cudaGetSymbolAddress((void**)&we1,  g_we1);
    cudaGetSymbolAddress((void**)&we2,  g_we2);
    cudaGetSymbolAddress((void**)&wm,   g_wm);
    cudaGetSymbolAddress((void**)&catH, g_catH);
    cudaGetSymbolAddress((void**)&catM, g_catM);
    cudaGetSymbolAddress((void**)&catL, g_catL);
    cudaGetSymbolAddress((void**)&d0h, g_d0h); cudaGetSymbolAddress((void**)&d0m, g_d0m);
    cudaGetSymbolAddress((void**)&d0l, g_d0l);
    cudaGetSymbolAddress((void**)&d1h, g_d1h); cudaGetSymbolAddress((void**)&d1m, g_d1m);
    cudaGetSymbolAddress((void**)&d1l, g_d1l);
    cudaGetSymbolAddress((void**)&d2h, g_d2h); cudaGetSymbolAddress((void**)&d2m, g_d2m);
    cudaGetSymbolAddress((void**)&d2l, g_d2l);

    // ---- prep ----
    normalize_rows_kernel<<<64, 128>>>(spk, spkn);
    normalize_rows_kernel<<<512, 128>>>(cb, cbn);
    gather_yv_kernel<<<MTOT, 128>>>(y, spkn, catH, catM, catL);
    wenc_kernel<<<(1024 * 39 * 5 + 255) / 256, 256>>>(ew0, we0, 39, 1024, 5);
    wenc_kernel<<<(512 * 1024 * 5 + 255) / 256, 256>>>(ew1, we1, 1024, 512, 5);
    wenc_kernel<<<(512 * 512 * 5 + 255) / 256, 256>>>(ew2, we2, 512, 512, 5);
    wenc_kernel<<<(128 * 512 + 255) / 256, 256>>>(mw, wm, 512, 128, 1);
    wsplit_dec<<<(1024 * 1280 + 255) / 256, 256>>>(dw0, d0h, d0m, d0l, 256, 1024, 128);
    wsplit_dec<<<(1024 * 3200 + 255) / 256, 256>>>(dw1, d1h, d1m, d1l, 640, 1024, 512);
    wsplit_dec<<<(39 * 3200 + 255) / 256, 256>>>(dw2, d2h, d2m, d2l, 640, 39, 512);

    // ---- encoder (R3-proven FFMA2, [B][C][T]) ----
    launch_conv(x, we0, eb0, bufA, 39, 39, 1024, 5, 1);
    gn_lrelu_kernel<<<dim3(TLEN / 256, 1024, BATCH), 256>>>(bufA, eg0, et0, 1024);

    launch_conv(bufA, we1, eb1, bufB, 1024, 1024, 512, 5, 1);
    gn_lrelu_kernel<<<dim3(TLEN / 256, 512, BATCH), 256>>>(bufB, eg1, et1, 512);

    launch_conv(bufB, we2, eb2, bufA, 512, 512, 512, 5, 1);
    gn_lrelu_kernel<<<dim3(TLEN / 256, 512, BATCH), 256>>>(bufA, eg2, et2, 512);

    launch_conv(bufA, wm, mb, z, 512, 512, 128, 1, 0);

    // ---- VQ -> cat[m][128..255] split3 ----
    vq_kernel<<<MTOT / 8, 256>>>(z, cbn, catH, catM, catL);

    // ---- decoder (mma.sync split3 GEMM, [m][C]) ----
    zero_stats_kernel<<<1, 32>>>();
    gemm_mma_kernel<0><<<dim3(8, MTOT / 128), 256, SMEM_P6>>>(
        catH, catM, catL, d0h, d0m, d0l, db0, bufA, 640, 256, 5, 1024, 1);
    gn_glu_split3<<<dim3(2, MTOT), 256>>>(bufA, dg0, dt0, catH, catM, catL);

    zero_stats_kernel<<<1, 32>>>();
    gemm_mma_kernel<0><<<dim3(8, MTOT / 128), 256, SMEM_P6>>>(
        catH, catM, catL, d1h, d1m, d1l, db1, bufA, 640, 640, 5, 1024, 1);
    gn_glu_split3<<<dim3(2, MTOT), 256>>>(bufA, dg1, dt1, catH, catM, catL);

    gemm_mma_kernel<2><<<dim3(1, MTOT / 128), 256, SMEM_P6>>>(
        catH, catM, catL, d2h, d2m, d2l, db2, out, 640, 640, 5, 39, 0);
}

// round 12
// speedup vs baseline: 1.8464x; 1.8464x over previous
#include <cuda_runtime.h>
#include <cuda_fp16.h>
#include <math.h>
#include <stdint.h>

#define BATCH 16
#define TLEN  2048
#define MTOT  (BATCH * TLEN)
#define LRELU_SLOPE 0.02f
#define GN_EPS 1e-5

typedef unsigned long long u64;
typedef unsigned int u32;
typedef unsigned short u16;

// ---------------- scratch ----------------
__device__ float g_bufA[(size_t)MTOT * 1024];     // enc [B][C][T] then dec [m][1024]
__device__ float g_bufB[(size_t)MTOT * 512];
__device__ float g_z   [(size_t)MTOT * 128];      // [B][128][T]
__device__ float g_spkn[64 * 128];
__device__ float g_cbn [512 * 128];
__device__ u16   g_catH[(size_t)MTOT * 640], g_catL[(size_t)MTOT * 640];
// encoder weights fp32 [CI][K][CO]
__device__ float g_we0[39 * 5 * 1024];
__device__ float g_we1[1024 * 5 * 512];
__device__ float g_we2[512 * 5 * 512];
__device__ float g_wm [512 * 128];
// decoder weights fp16 split2 [co][k*CS+ci]
__device__ u16 g_d0h[1024 * 1280], g_d0l[1024 * 1280];
__device__ u16 g_d1h[1024 * 3200], g_d1l[1024 * 3200];
__device__ u16 g_d2h[39 * 3200],   g_d2l[39 * 3200];
__device__ double g_stats[2 * BATCH];

// ---------------- common helpers ----------------
__device__ __forceinline__ u64 ffma2(u64 a, u64 b, u64 c) {
    u64 d; asm("fma.rn.f32x2 %0, %1, %2, %3;" : "=l"(d) : "l"(a), "l"(b), "l"(c));
    return d;
}
__device__ __forceinline__ float2 unpack2(u64 v) {
    float2 f; asm("mov.b64 {%0, %1}, %2;" : "=f"(f.x), "=f"(f.y) : "l"(v));
    return f;
}
__device__ __forceinline__ void cp_async4(void* smem, const float* g, bool p) {
    unsigned s = (unsigned)__cvta_generic_to_shared(smem);
    int sz = p ? 4 : 0;
    asm volatile("cp.async.ca.shared.global [%0], [%1], 4, %2;"
                 :: "r"(s), "l"(g), "r"(sz));
}
__device__ __forceinline__ u32 smem_u32(const void* p) {
    u32 a;
    asm("{ .reg .u64 t; cvta.to.shared.u64 t, %1; cvt.u32.u64 %0, t; }"
        : "=r"(a) : "l"(p));
    return a;
}
__device__ __forceinline__ void cp_async16(u32 saddr, const void* g, bool p) {
    int sz = p ? 16 : 0;
    asm volatile("cp.async.cg.shared.global [%0], [%1], 16, %2;"
                 :: "r"(saddr), "l"(g), "r"(sz));
}
#define CP_COMMIT() asm volatile("cp.async.commit_group;" ::: "memory")
#define CP_WAIT(n)  asm volatile("cp.async.wait_group %0;" :: "n"(n) : "memory")
#define SW128(o) ((u32)(o) ^ ((((u32)(o)) >> 3) & 0x70u))

__device__ __forceinline__ void ldsm4(u32* r, u32 addr) {
    asm volatile("ldmatrix.sync.aligned.m8n8.x4.shared.b16 {%0,%1,%2,%3}, [%4];"
                 : "=r"(r[0]), "=r"(r[1]), "=r"(r[2]), "=r"(r[3]) : "r"(addr));
}
__device__ __forceinline__ void mma_f16(float* d, const u32* a, const u32* b) {
    asm volatile(
        "mma.sync.aligned.m16n8k16.row.col.f32.f16.f16.f32 "
        "{%0,%1,%2,%3},{%4,%5,%6,%7},{%8,%9},{%0,%1,%2,%3};"
        : "+f"(d[0]), "+f"(d[1]), "+f"(d[2]), "+f"(d[3])
        : "r"(a[0]), "r"(a[1]), "r"(a[2]), "r"(a[3]), "r"(b[0]), "r"(b[1]));
}
// fp16 2-way split: ~22-bit operand
__device__ __forceinline__ void split2h(float v, u16* H, u16* L, size_t i) {
    __half h = __float2half_rn(v);
    float r = v - __half2float(h);
    __half l = __float2half_rn(r);
    H[i] = *(u16*)&h; L[i] = *(u16*)&l;
}

// ---------------- prep kernels ----------------
__global__ void normalize_rows_kernel(const float* __restrict__ in,
                                      float* __restrict__ out) {
    int r = blockIdx.x, tid = threadIdx.x;
    float v = in[r * 128 + tid];
    __shared__ float sh[128];
    sh[tid] = v * v;
    __syncthreads();
    for (int off = 64; off > 0; off >>= 1) {
        if (tid < off) sh[tid] += sh[tid + off];
        __syncthreads();
    }
    out[r * 128 + tid] = v * rsqrtf(sh[0] + 1e-12f);
}

// encoder Conv1d weight [CO][CI][K] -> [CI][K][CO] fp32
__global__ void wenc_kernel(const float* __restrict__ W, float* __restrict__ Wp,
                            int CI, int CO, int K) {
    int idx = blockIdx.x * 256 + threadIdx.x;
    if (idx >= CO * CI * K) return;
    int k  = idx % K;
    int ci = (idx / K) % CI;
    int co = idx / (K * CI);
    Wp[((size_t)ci * K + k) * CO + co] = W[idx];
}

// decoder ConvTranspose [CIo][CO][5] -> fp16 split2 [co][k*CS+ci] (flip+remap)
__global__ void wsplit_dec(const float* __restrict__ W, u16* Wh, u16* Wl,
                           int CS, int CO, int split) {
    int i = blockIdx.x * 256 + threadIdx.x;
    if (i >= CO * 5 * CS) return;
    int co = i / (5 * CS), j = i % (5 * CS);
    int k = j / CS, ci = j % CS;
    int ci0 = (ci < 128) ? ci + split : ci - 128;
    float v = W[((size_t)ci0 * CO + co) * 5 + (4 - k)];
    split2h(v, Wh, Wl, i);
}

__global__ void gather_yv_kernel(const int* __restrict__ y,
                                 const float* __restrict__ spkn,
                                 u16* __restrict__ H, u16* __restrict__ L) {
    int m = blockIdx.x;
    int idx = y[m];
    split2h(spkn[idx * 128 + threadIdx.x], H, L, (size_t)m * 640 + threadIdx.x);
}

__global__ void zero_stats_kernel() {
    if (threadIdx.x < 2 * BATCH) g_stats[threadIdx.x] = 0.0;
}

// ================= R3/R10-proven FFMA2 encoder conv ([B][C][T]) ===========
template <int K>
__device__ __forceinline__ void stage_tiles(
    const float* __restrict__ Xb, const float* __restrict__ Wp,
    float* XsBuf, float* WsBuf, int cb, int CI, int CO, int t0, int o0, int tid) {
    const int BM = 128, XR = 128 + (K - 1), PAD = (K - 1) / 2;
    for (int i = tid; i < 8 * XR; i += 256) {
        int ci = i / XR, t = i % XR;
        int gci = cb + ci, gt = t0 + t - PAD;
        bool p = (gci < CI) && ((unsigned)gt < (unsigned)TLEN);
        const float* src = p ? (Xb + (size_t)gci * TLEN + gt) : Xb;
        cp_async4(XsBuf + ci * XR + t, src, p);
    }
    for (int i = tid; i < 8 * K * BM; i += 256) {
        int ci = i / (K * BM);
        int r  = i % (K * BM);
        int k = r / BM, o = r % BM;
        int gci = cb + ci, go = o0 + o;
        bool p = (gci < CI) && (go < CO);
        const float* src = p ? (Wp + ((size_t)gci * K + k) * CO + go) : Wp;
        cp_async4(WsBuf + i, src, p);
    }
}

template <int K>
__global__ void __launch_bounds__(256, 2)
conv_f2_kernel(const float* __restrict__ X, const float* __restrict__ Wp,
               const float* __restrict__ bias, float* __restrict__ Y,
               int CI, int CBx, int CO, int doStats) {
    const int BM = 128, BN = 128, BK = 8;
    const int XR = BN + (K - 1);
    const int NX = 8 + K - 1;
    const int XSZ = BK * XR;
    const int WSZ = BK * K * BM;

    extern __shared__ float sm[];
    float* Xs0 = sm;
    float* Ws0 = sm + 2 * XSZ;
    float* red = Ws0 + 2 * WSZ;

    int b  = blockIdx.z;
    int t0 = blockIdx.x * BN;
    int o0 = blockIdx.y * BM;
    int tid = threadIdx.x;
    int warp = tid >> 5, lane = tid & 31;
    int wco = warp & 1, wt = warp >> 1;
    int lco = lane >> 2, lt = lane & 3;
    int tco = wco * 64 + lco * 8;
    int tt  = wt * 32 + lt * 8;

    const float* Xb = X + (size_t)b * CBx * TLEN;
    int nchunk = (CI + BK - 1) / BK;

    u64 acc[4][8];
#pragma unroll
    for (int p = 0; p < 4; p++)
#pragma unroll
        for (int j = 0; j < 8; j++) acc[p][j] = 0ull;

    stage_tiles<K>(Xb, Wp, Xs0, Ws0, 0, CI, CO, t0, o0, tid);
    CP_COMMIT();

    for (int c = 0; c < nchunk; c++) {
        int buf = c & 1;
        if (c + 1 < nchunk) {
            stage_tiles<K>(Xb, Wp, Xs0 + (buf ^ 1) * XSZ, Ws0 + (buf ^ 1) * WSZ,
                           (c + 1) * BK, CI, CO, t0, o0, tid);
            CP_COMMIT();
            CP_WAIT(1);
        } else {
            CP_WAIT(0);
        }
        __syncthreads();

        const float* Xsb = Xs0 + buf * XSZ;
        const float* Wsb = Ws0 + buf * WSZ;
#pragma unroll
        for (int ci = 0; ci < BK; ci++) {
            u64 xs[NX];
#pragma unroll
            for (int v4 = 0; v4 < (NX + 3) / 4; v4++) {
                float4 xv = *(const float4*)&Xsb[ci * XR + tt + v4 * 4];
                if (v4 * 4 + 0 < NX) { u64 r; asm("mov.b64 %0,{%1,%1};":"=l"(r):"f"(xv.x)); xs[v4*4+0]=r; }
                if (v4 * 4 + 1 < NX) { u64 r; asm("mov.b64 %0,{%1,%1};":"=l"(r):"f"(xv.y)); xs[v4*4+1]=r; }
                if (v4 * 4 + 2 < NX) { u64 r; asm("mov.b64 %0,{%1,%1};":"=l"(r):"f"(xv.z)); xs[v4*4+2]=r; }
                if (v4 * 4 + 3 < NX) { u64 r; asm("mov.b64 %0,{%1,%1};":"=l"(r):"f"(xv.w)); xs[v4*4+3]=r; }
            }
#pragma unroll
            for (int k = 0; k < K; k++) {
                const float* wrow = Wsb + (ci * K + k) * BM + tco;
                ulonglong2 wa = *(const ulonglong2*)(wrow);
                ulonglong2 wb = *(const ulonglong2*)(wrow + 4);
                u64 wp[4] = {wa.x, wa.y, wb.x, wb.y};
#pragma unroll
                for (int p = 0; p < 4; p++)
#pragma unroll
                    for (int j = 0; j < 8; j++)
                        acc[p][j] = ffma2(wp[p], xs[j + k], acc[p][j]);
            }
        }
        __syncthreads();
    }

    int gt = t0 + tt;
    float ssum = 0.f, ssq = 0.f;
#pragma unroll
    for (int p = 0; p < 4; p++) {
        int oa = o0 + tco + 2 * p;
        int ob = oa + 1;
        bool va = oa < CO, vb = ob < CO;
        float ba = va ? bias[oa] : 0.f;
        float bb = vb ? bias[ob] : 0.f;
        float fa[8], fb[8];
#pragma unroll
        for (int j = 0; j < 8; j++) {
            float2 v = unpack2(acc[p][j]);
            fa[j] = v.x + ba; fb[j] = v.y + bb;
            if (va) { ssum += fa[j]; ssq += fa[j] * fa[j]; }
            if (vb) { ssum += fb[j]; ssq += fb[j] * fb[j]; }
        }
        if (va) {
            float* rowa = Y + ((size_t)b * CO + oa) * TLEN + gt;
            *(float4*)(rowa)     = make_float4(fa[0], fa[1], fa[2], fa[3]);
            *(float4*)(rowa + 4) = make_float4(fa[4], fa[5], fa[6], fa[7]);
        }
        if (vb) {
            float* rowb = Y + ((size_t)b * CO + ob) * TLEN + gt;
            *(float4*)(rowb)     = make_float4(fb[0], fb[1], fb[2], fb[3]);
            *(float4*)(rowb + 4) = make_float4(fb[4], fb[5], fb[6], fb[7]);
        }
    }
    if (doStats) {
#pragma unroll
        for (int off = 16; off > 0; off >>= 1) {
            ssum += __shfl_down_sync(0xffffffffu, ssum, off);
            ssq  += __shfl_down_sync(0xffffffffu, ssq,  off);
        }
        if (lane == 0) { red[warp] = ssum; red[8 + warp] = ssq; }
        __syncthreads();
        if (tid == 0) {
            double s = 0.0, s2 = 0.0;
            for (int w = 0; w < 8; w++) { s += red[w]; s2 += red[8 + w]; }
            atomicAdd(&g_stats[2 * b],     s);
            atomicAdd(&g_stats[2 * b + 1], s2);
        }
    }
}

__global__ void gn_lrelu_kernel(float* __restrict__ X,
                                const float* __restrict__ g,
                                const float* __restrict__ bt, int C) {
    int b = blockIdx.z, c = blockIdx.y;
    int t = blockIdx.x * 256 + threadIdx.x;
    double N = (double)C * TLEN;
    double mean = g_stats[2 * b] / N;
    double var  = g_stats[2 * b + 1] / N - mean * mean;
    float rstd = (float)rsqrt(var + GN_EPS);
    float sc = g[c] * rstd;
    float sh = bt[c] - (float)mean * sc;
    size_t idx = ((size_t)b * C + c) * TLEN + t;
    float yv = X[idx] * sc + sh;
    X[idx] = yv >= 0.f ? yv : LRELU_SLOPE * yv;
}

// VQ on [B][128][T] z (R3/R10-proven); emits split2 zq into cat[m][128..255]
__global__ void vq_kernel(const float* __restrict__ z,
                          const float* __restrict__ cbn,
                          u16* __restrict__ catH, u16* __restrict__ catL) {
    __shared__ float zs[8][128];
    int warp = threadIdx.x >> 5, lane = threadIdx.x & 31;
    int pos = blockIdx.x * 8 + warp;
    int b = pos / TLEN, t = pos % TLEN;

    for (int d = lane; d < 128; d += 32)
        zs[warp][d] = z[((size_t)b * 128 + d) * TLEN + t];
    __syncwarp();

    const float4* zs4 = (const float4*)zs[warp];
    float best = -1e30f;
    int bk = 0;
    for (int kk = 0; kk < 16; kk++) {
        int k = kk * 32 + lane;
        const float4* cb4 = (const float4*)(cbn + (size_t)k * 128);
        float s = 0.f;
#pragma unroll
        for (int d4 = 0; d4 < 32; d4++) {
            float4 zv = zs4[d4], cv = cb4[d4];
            s += zv.x * cv.x + zv.y * cv.y + zv.z * cv.z + zv.w * cv.w;
        }
        if (s > best || (s == best && k < bk)) { best = s; bk = k; }
    }
    for (int off = 16; off > 0; off >>= 1) {
        float ob = __shfl_down_sync(0xffffffff, best, off);
        int   ok = __shfl_down_sync(0xffffffff, bk,   off);
        if (ob > best || (ob == best && ok < bk)) { best = ob; bk = ok; }
    }
    bk = __shfl_sync(0xffffffff, bk, 0);
    for (int d = lane; d < 128; d += 32)
        split2h(cbn[(size_t)bk * 128 + d], catH, catL,
                (size_t)pos * 640 + 128 + d);
}

// ================= decoder: fp16-split2 mma.sync GEMM (3 products) =======
// MODE 0: Y[m][CO] (+GN stats).  MODE 2: Y[b][CO][t].
template <int MODE>
__global__ void __launch_bounds__(256)
gemm_mma_kernel(const u16* __restrict__ AH, const u16* __restrict__ AL,
                const u16* __restrict__ WH, const u16* __restrict__ WL,
                const float* __restrict__ bias, float* __restrict__ Y,
                int RS, int CS, int K, int CO, int doStats) {
    const int BUFB = 4 * 16384;  // AH|AL|WH|WL per stage
    extern __shared__ char dsm[];
    __shared__ float s_bias[128];
    __shared__ float s_red[16];

    const int PAD = (K - 1) / 2;
    const int KP = K * CS;
    const int cs64 = CS >> 6;
    const int nch = K * cs64;

    int tid = threadIdx.x, wid = tid >> 5, lane = tid & 31;
    int co0 = blockIdx.x * 128, m0 = blockIdx.y * 128;
    u32 sb = smem_u32(dsm);

    auto stage = [&](int c, int buf) {
        int k = c / cs64;
        int cib = (c - k * cs64) << 6;
        int dk = k - PAD;
        u32 base = sb + buf * BUFB;
        for (int i = tid; i < 1024; i += 256) {
            int r = i >> 3, g7 = i & 7;
            u32 soff = SW128(r * 128 + g7 * 16);
            int m = m0 + r;
            int tt = (m & 2047) + dk;
            bool pv = (unsigned)tt < 2048u;
            size_t aoff = (size_t)(m + dk) * RS + cib + g7 * 8;
            cp_async16(base + soff, pv ? AH + aoff : AH, pv);
            cp_async16(base + 16384 + soff, pv ? AL + aoff : AL, pv);
            int co = co0 + r;
            bool pw = co < CO;
            size_t woff = (size_t)co * KP + c * 64 + g7 * 8;
            cp_async16(base + 32768 + soff, pw ? WH + woff : WH, pw);
            cp_async16(base + 49152 + soff, pw ? WL + woff : WL, pw);
        }
        CP_COMMIT();
    };

    float acc[2][8][4];
#pragma unroll
    for (int a = 0; a < 2; a++)
#pragma unroll
        for (int b = 0; b < 8; b++)
#pragma unroll
            for (int c = 0; c < 4; c++) acc[a][b][c] = 0.f;

    int wm = (wid & 3) * 32, wn = (wid >> 2) * 64;
    int quad = lane >> 3, l7 = lane & 7;
    int arow = wm + (quad & 1) * 8 + l7;
    int acolb = (quad >> 1) * 16;
    int brow = wn + (quad >> 1) * 8 + l7;
    int bcolb = (quad & 1) * 16;

    stage(0, 0);
    if (nch > 1) stage(1, 1);

    for (int c = 0; c < nch; c++) {
        int buf = c % 3;
        if (c + 2 < nch) { stage(c + 2, (c + 2) % 3); CP_WAIT(2); }
        else if (c + 1 < nch) { CP_WAIT(1); }
        else { CP_WAIT(0); }
        __syncthreads();

        u32 baseA = sb + buf * BUFB;
        u32 baseW = baseA + 32768;
#pragma unroll
        for (int ks = 0; ks < 4; ks++) {
            u32 ah[2][4], al[2][4];
#pragma unroll
            for (int mt = 0; mt < 2; mt++) {
                u32 off = SW128((arow + mt * 16) * 128 + acolb + ks * 32);
                ldsm4(ah[mt], baseA + off);
                ldsm4(al[mt], baseA + 16384 + off);
            }
#pragma unroll
            for (int nt2 = 0; nt2 < 4; nt2++) {
                u32 off = SW128((brow + nt2 * 16) * 128 + bcolb + ks * 32);
                u32 bh[4], bl[4];
                ldsm4(bh, baseW + off);
                ldsm4(bl, baseW + 16384 + off);
#pragma unroll
                for (int mt = 0; mt < 2; mt++) {
                    mma_f16(acc[mt][2 * nt2],     ah[mt], bh);
                    mma_f16(acc[mt][2 * nt2],     ah[mt], bl);
                    mma_f16(acc[mt][2 * nt2],     al[mt], bh);
                    mma_f16(acc[mt][2 * nt2 + 1], ah[mt], bh + 2);
                    mma_f16(acc[mt][2 * nt2 + 1], ah[mt], bl + 2);
                    mma_f16(acc[mt][2 * nt2 + 1], al[mt], bh + 2);
                }
            }
        }
        __syncthreads();
    }

    if (tid < 128) {
        int co = co0 + tid;
        s_bias[tid] = (co < CO) ? bias[co] : 0.f;
    }
    __syncthreads();

    int g = lane >> 2, tg = lane & 3;
    float ssum = 0.f, ssq = 0.f;
#pragma unroll
    for (int mt = 0; mt < 2; mt++) {
#pragma unroll
        for (int nt = 0; nt < 8; nt++) {
            int colb = wn + nt * 8 + tg * 2;
            float b0 = s_bias[colb], b1 = s_bias[colb + 1];
            float f00 = acc[mt][nt][0] + b0, f01 = acc[mt][nt][1] + b1;
            float f10 = acc[mt][nt][2] + b0, f11 = acc[mt][nt][3] + b1;
            int m1 = m0 + wm + mt * 16 + g;
            int co = co0 + colb;
            if (MODE == 0) {
                *(float2*)&Y[(size_t)m1 * CO + co] = make_float2(f00, f01);
                *(float2*)&Y[(size_t)(m1 + 8) * CO + co] = make_float2(f10, f11);
                ssum += f00 + f01 + f10 + f11;
                ssq += f00 * f00 + f01 * f01 + f10 * f10 + f11 * f11;
            } else {
                int b = m1 >> 11, t = m1 & 2047;
                if (co < CO) {
                    Y[((size_t)b * CO + co) * TLEN + t] = f00;
                    Y[((size_t)b * CO + co) * TLEN + t + 8] = f10;
                }
                if (co + 1 < CO) {
                    Y[((size_t)b * CO + co + 1) * TLEN + t] = f01;
                    Y[((size_t)b * CO + co + 1) * TLEN + t + 8] = f11;
                }
            }
        }
    }

    if (MODE == 0 && doStats) {
#pragma unroll
        for (int off = 16; off > 0; off >>= 1) {
            ssum += __shfl_down_sync(0xffffffffu, ssum, off);
            ssq  += __shfl_down_sync(0xffffffffu, ssq,  off);
        }
        if (lane == 0) { s_red[wid] = ssum; s_red[8 + wid] = ssq; }
        __syncthreads();
        if (tid == 0) {
            double s = 0.0, s2 = 0.0;
            for (int w = 0; w < 8; w++) { s += s_red[w]; s2 += s_red[8 + w]; }
            int b = m0 >> 11;
            atomicAdd(&g_stats[2 * b], s);
            atomicAdd(&g_stats[2 * b + 1], s2);
        }
    }
}

__global__ void gn_glu_split2(const float* __restrict__ X,
                              const float* __restrict__ g,
                              const float* __restrict__ bt,
                              u16* __restrict__ catH, u16* __restrict__ catL) {
    int m = blockIdx.y;
    int c = blockIdx.x * 256 + threadIdx.x;  // < 512
    int b = m >> 11;
    double N = 1024.0 * TLEN;
    double mean = g_stats[2 * b] / N;
    double var  = g_stats[2 * b + 1] / N - mean * mean;
    float rstd = (float)rsqrt(var + GN_EPS);
    float mf = (float)mean;
    float a  = X[(size_t)m * 1024 + c];
    float gv = X[(size_t)m * 1024 + 512 + c];
    float na = (a  - mf) * rstd * g[c]       + bt[c];
    float ng = (gv - mf) * rstd * g[c + 512] + bt[c + 512];
    float v = na / (1.f + expf(-ng));
    split2h(v, catH, catL, (size_t)m * 640 + 128 + c);
}

// ---------------- host ----------------
static const int SMEM_K5 = (2 * (8 * 132) + 2 * (8 * 5 * 128) + 16) * 4;
static const int SMEM_K1 = (2 * (8 * 128) + 2 * (8 * 1 * 128) + 16) * 4;
static const int SMEM_G  = 3 * 4 * 16384;  // 196608

static void launch_conv(const float* X, const float* Wp, const float* b,
                        float* Y, int CI, int CBx, int CO, int K, int doStats) {
    dim3 grid(TLEN / 128, (CO + 127) / 128, BATCH);
    if (doStats) zero_stats_kernel<<<1, 32>>>();
    if (K == 5)
        conv_f2_kernel<5><<<grid, 256, SMEM_K5>>>(X, Wp, b, Y, CI, CBx, CO, doStats);
    else
        conv_f2_kernel<1><<<grid, 256, SMEM_K1>>>(X, Wp, b, Y, CI, CBx, CO, doStats);
}

extern "C" void kernel_launch(void* const* d_in, const int* in_sizes, int n_in,
                              void* d_out, int out_size) {
    const float* x    = (const float*)d_in[0];
    const int*   y    = (const int*)  d_in[1];
    const float* spk  = (const float*)d_in[2];
    const float* cb   = (const float*)d_in[3];
    const float *ew0 = (const float*)d_in[4],  *eb0 = (const float*)d_in[5];
    const float *eg0 = (const float*)d_in[6],  *et0 = (const float*)d_in[7];
    const float *ew1 = (const float*)d_in[8],  *eb1 = (const float*)d_in[9];
    const float *eg1 = (const float*)d_in[10], *et1 = (const float*)d_in[11];
    const float *ew2 = (const float*)d_in[12], *eb2 = (const float*)d_in[13];
    const float *eg2 = (const float*)d_in[14], *et2 = (const float*)d_in[15];
    const float *mw  = (const float*)d_in[16], *mb  = (const float*)d_in[17];
    const float *dw0 = (const float*)d_in[18], *db0 = (const float*)d_in[19];
    const float *dg0 = (const float*)d_in[20], *dt0 = (const float*)d_in[21];
    const float *dw1 = (const float*)d_in[22], *db1 = (const float*)d_in[23];
    const float *dg1 = (const float*)d_in[24], *dt1 = (const float*)d_in[25];
    const float *dw2 = (const float*)d_in[26], *db2 = (const float*)d_in[27];
    float* out = (float*)d_out;

    cudaFuncSetAttribute(conv_f2_kernel<5>,
                         cudaFuncAttributeMaxDynamicSharedMemorySize, SMEM_K5);
    cudaFuncSetAttribute(conv_f2_kernel<1>,
                         cudaFuncAttributeMaxDynamicSharedMemorySize, SMEM_K1);
    cudaFuncSetAttribute(gemm_mma_kernel<0>,
                         cudaFuncAttributeMaxDynamicSharedMemorySize, SMEM_G);
    cudaFuncSetAttribute(gemm_mma_kernel<2>,
                         cudaFuncAttributeMaxDynamicSharedMemorySize, SMEM_G);

    float *bufA, *bufB, *z, *spkn, *cbn, *we0, *we1, *we2, *wm;
    u16 *catH, *catL;
    u16 *d0h, *d0l, *d1h, *d1l, *d2h, *d2l;
    cudaGetSymbolAddress((void**)&bufA, g_bufA);
    cudaGetSymbolAddress((void**)&bufB, g_bufB);
    cudaGetSymbolAddress((void**)&z,    g_z);
    cudaGetSymbolAddress((void**)&spkn, g_spkn);
    cudaGetSymbolAddress((void**)&cbn,  g_cbn);
    cudaGetSymbolAddress((void**)&we0,  g_we0);
    cudaGetSymbolAddress((void**)&we1,  g_we1);
    cudaGetSymbolAddress((void**)&we2,  g_we2);
    cudaGetSymbolAddress((void**)&wm,   g_wm);
    cudaGetSymbolAddress((void**)&catH, g_catH);
    cudaGetSymbolAddress((void**)&catL, g_catL);
    cudaGetSymbolAddress((void**)&d0h, g_d0h); cudaGetSymbolAddress((void**)&d0l, g_d0l);
    cudaGetSymbolAddress((void**)&d1h, g_d1h); cudaGetSymbolAddress((void**)&d1l, g_d1l);
    cudaGetSymbolAddress((void**)&d2h, g_d2h); cudaGetSymbolAddress((void**)&d2l, g_d2l);

    // ---- prep ----
    normalize_rows_kernel<<<64, 128>>>(spk, spkn);
    normalize_rows_kernel<<<512, 128>>>(cb, cbn);
    gather_yv_kernel<<<MTOT, 128>>>(y, spkn, catH, catL);
    wenc_kernel<<<(1024 * 39 * 5 + 255) / 256, 256>>>(ew0, we0, 39, 1024, 5);
    wenc_kernel<<<(512 * 1024 * 5 + 255) / 256, 256>>>(ew1, we1, 1024, 512, 5);
    wenc_kernel<<<(512 * 512 * 5 + 255) / 256, 256>>>(ew2, we2, 512, 512, 5);
    wenc_kernel<<<(128 * 512 + 255) / 256, 256>>>(mw, wm, 512, 128, 1);
    wsplit_dec<<<(1024 * 1280 + 255) / 256, 256>>>(dw0, d0h, d0l, 256, 1024, 128);
    wsplit_dec<<<(1024 * 3200 + 255) / 256, 256>>>(dw1, d1h, d1l, 640, 1024, 512);
    wsplit_dec<<<(39 * 3200 + 255) / 256, 256>>>(dw2, d2h, d2l, 640, 39, 512);

    // ---- encoder (proven FFMA2, [B][C][T]) ----
    launch_conv(x, we0, eb0, bufA, 39, 39, 1024, 5, 1);
    gn_lrelu_kernel<<<dim3(TLEN / 256, 1024, BATCH), 256>>>(bufA, eg0, et0, 1024);

    launch_conv(bufA, we1, eb1, bufB, 1024, 1024, 512, 5, 1);
    gn_lrelu_kernel<<<dim3(TLEN / 256, 512, BATCH), 256>>>(bufB, eg1, et1, 512);

    launch_conv(bufB, we2, eb2, bufA, 512, 512, 512, 5, 1);
    gn_lrelu_kernel<<<dim3(TLEN / 256, 512, BATCH), 256>>>(bufA, eg2, et2, 512);

    launch_conv(bufA, wm, mb, z, 512, 512, 128, 1, 0);

    // ---- VQ -> cat[m][128..255] split2 ----
    vq_kernel<<<MTOT / 8, 256>>>(z, cbn, catH, catL);

    // ---- decoder (fp16-split2 mma GEMM, [m][C]) ----
    zero_stats_kernel<<<1, 32>>>();
    gemm_mma_kernel<0><<<dim3(8, MTOT / 128), 256, SMEM_G>>>(
        catH, catL, d0h, d0l, db0, bufA, 640, 256, 5, 1024, 1);
    gn_glu_split2<<<dim3(2, MTOT), 256>>>(bufA, dg0, dt0, catH, catL);

    zero_stats_kernel<<<1, 32>>>();
    gemm_mma_kernel<0><<<dim3(8, MTOT / 128), 256, SMEM_G>>>(
        catH, catL, d1h, d1l, db1, bufA, 640, 640, 5, 1024, 1);
    gn_glu_split2<<<dim3(2, MTOT), 256>>>(bufA, dg1, dt1, catH, catL);

    gemm_mma_kernel<2><<<dim3(1, MTOT / 128), 256, SMEM_G>>>(
        catH, catL, d2h, d2l, db2, out, 640, 640, 5, 39, 0);
}

// round 14
// speedup vs baseline: 2.1189x; 1.1476x over previous
#include <cuda_runtime.h>
#include <cuda_fp16.h>
#include <math.h>
#include <stdint.h>

#define BATCH 16
#define TLEN  2048
#define MTOT  (BATCH * TLEN)
#define LRELU_SLOPE 0.02f
#define GN_EPS 1e-5

typedef unsigned long long u64;
typedef unsigned int u32;
typedef unsigned short u16;

// ---------------- scratch ----------------
__device__ float g_bufA[(size_t)MTOT * 1024];     // [B][1024][T] / [m][C] reuse
__device__ float g_bufB[(size_t)MTOT * 512];      // [B][512][T]
__device__ float g_z   [(size_t)MTOT * 128];      // [B][128][T]
__device__ float g_spkn[64 * 128];
__device__ float g_cbn [512 * 128];
__device__ u16   g_aH[(size_t)MTOT * 512], g_aL[(size_t)MTOT * 512];
__device__ u16   g_bH[(size_t)MTOT * 512], g_bL[(size_t)MTOT * 512];
__device__ u16   g_catH[(size_t)MTOT * 640], g_catL[(size_t)MTOT * 640];
// encoder weights fp32 [CI][K][CO] (L0, L1)
__device__ float g_we0[39 * 5 * 1024];
__device__ float g_we1[1024 * 5 * 512];
// enc L2 / 1x1 + decoder weights fp16 split2 [co][k*CS+ci]
__device__ u16 g_w2h[512 * 2560],  g_w2l[512 * 2560];
__device__ u16 g_wmh[128 * 512],   g_wml[128 * 512];
__device__ u16 g_d0h[1024 * 1280], g_d0l[1024 * 1280];
__device__ u16 g_d1h[1024 * 3200], g_d1l[1024 * 3200];
__device__ u16 g_d2h[39 * 3200],   g_d2l[39 * 3200];
__device__ double g_stats[2 * BATCH];

// ---------------- common helpers ----------------
__device__ __forceinline__ u64 ffma2(u64 a, u64 b, u64 c) {
    u64 d; asm("fma.rn.f32x2 %0, %1, %2, %3;" : "=l"(d) : "l"(a), "l"(b), "l"(c));
    return d;
}
__device__ __forceinline__ float2 unpack2(u64 v) {
    float2 f; asm("mov.b64 {%0, %1}, %2;" : "=f"(f.x), "=f"(f.y) : "l"(v));
    return f;
}
__device__ __forceinline__ void cp_async4(void* smem, const float* g, bool p) {
    unsigned s = (unsigned)__cvta_generic_to_shared(smem);
    int sz = p ? 4 : 0;
    asm volatile("cp.async.ca.shared.global [%0], [%1], 4, %2;"
                 :: "r"(s), "l"(g), "r"(sz));
}
__device__ __forceinline__ u32 smem_u32(const void* p) {
    u32 a;
    asm("{ .reg .u64 t; cvta.to.shared.u64 t, %1; cvt.u32.u64 %0, t; }"
        : "=r"(a) : "l"(p));
    return a;
}
__device__ __forceinline__ void cp_async16(u32 saddr, const void* g, bool p) {
    int sz = p ? 16 : 0;
    asm volatile("cp.async.cg.shared.global [%0], [%1], 16, %2;"
                 :: "r"(saddr), "l"(g), "r"(sz));
}
#define CP_COMMIT() asm volatile("cp.async.commit_group;" ::: "memory")
#define CP_WAIT(n)  asm volatile("cp.async.wait_group %0;" :: "n"(n) : "memory")
#define SW128(o) ((u32)(o) ^ ((((u32)(o)) >> 3) & 0x70u))

__device__ __forceinline__ void ldsm4(u32* r, u32 addr) {
    asm volatile("ldmatrix.sync.aligned.m8n8.x4.shared.b16 {%0,%1,%2,%3}, [%4];"
                 : "=r"(r[0]), "=r"(r[1]), "=r"(r[2]), "=r"(r[3]) : "r"(addr));
}
__device__ __forceinline__ void mma_f16(float* d, const u32* a, const u32* b) {
    asm volatile(
        "mma.sync.aligned.m16n8k16.row.col.f32.f16.f16.f32 "
        "{%0,%1,%2,%3},{%4,%5,%6,%7},{%8,%9},{%0,%1,%2,%3};"
        : "+f"(d[0]), "+f"(d[1]), "+f"(d[2]), "+f"(d[3])
        : "r"(a[0]), "r"(a[1]), "r"(a[2]), "r"(a[3]), "r"(b[0]), "r"(b[1]));
}
// fp16 2-way split: ~22-bit operand
__device__ __forceinline__ void split2h(float v, u16* H, u16* L, size_t i) {
    __half h = __float2half_rn(v);
    float r = v - __half2float(h);
    __half l = __float2half_rn(r);
    H[i] = *(u16*)&h; L[i] = *(u16*)&l;
}

// ---------------- prep kernels ----------------
__global__ void normalize_rows_kernel(const float* __restrict__ in,
                                      float* __restrict__ out) {
    int r = blockIdx.x, tid = threadIdx.x;
    float v = in[r * 128 + tid];
    __shared__ float sh[128];
    sh[tid] = v * v;
    __syncthreads();
    for (int off = 64; off > 0; off >>= 1) {
        if (tid < off) sh[tid] += sh[tid + off];
        __syncthreads();
    }
    out[r * 128 + tid] = v * rsqrtf(sh[0] + 1e-12f);
}

__global__ void wenc_kernel(const float* __restrict__ W, float* __restrict__ Wp,
                            int CI, int CO, int K) {
    int idx = blockIdx.x * 256 + threadIdx.x;
    if (idx >= CO * CI * K) return;
    int k  = idx % K;
    int ci = (idx / K) % CI;
    int co = idx / (K * CI);
    Wp[((size_t)ci * K + k) * CO + co] = W[idx];
}

// encoder weight [CO][CI][K] -> fp16 split [co][k*CS+ci]
__global__ void wsplit_enc_h(const float* __restrict__ W, u16* Wh, u16* Wl,
                             int CI, int CS, int CO, int K) {
    int i = blockIdx.x * 256 + threadIdx.x;
    if (i >= CO * K * CS) return;
    int co = i / (K * CS), j = i % (K * CS);
    int k = j / CS, ci = j % CS;
    float v = (ci < CI) ? W[((size_t)co * CI + ci) * K + k] : 0.f;
    split2h(v, Wh, Wl, i);
}

__global__ void wsplit_dec(const float* __restrict__ W, u16* Wh, u16* Wl,
                           int CS, int CO, int split) {
    int i = blockIdx.x * 256 + threadIdx.x;
    if (i >= CO * 5 * CS) return;
    int co = i / (5 * CS), j = i % (5 * CS);
    int k = j / CS, ci = j % CS;
    int ci0 = (ci < 128) ? ci + split : ci - 128;
    float v = W[((size_t)ci0 * CO + co) * 5 + (4 - k)];
    split2h(v, Wh, Wl, i);
}

__global__ void gather_yv_kernel(const int* __restrict__ y,
                                 const float* __restrict__ spkn,
                                 u16* __restrict__ H, u16* __restrict__ L) {
    int m = blockIdx.x;
    int idx = y[m];
    split2h(spkn[idx * 128 + threadIdx.x], H, L, (size_t)m * 640 + threadIdx.x);
}

__global__ void zero_stats_kernel() {
    if (threadIdx.x < 2 * BATCH) g_stats[threadIdx.x] = 0.0;
}

// ================= FFMA2 encoder conv ([B][C][T]) — proven ===============
template <int K>
__device__ __forceinline__ void stage_tiles(
    const float* __restrict__ Xb, const float* __restrict__ Wp,
    float* XsBuf, float* WsBuf, int cb, int CI, int CO, int t0, int o0, int tid) {
    const int BM = 128, XR = 128 + (K - 1), PAD = (K - 1) / 2;
    for (int i = tid; i < 8 * XR; i += 256) {
        int ci = i / XR, t = i % XR;
        int gci = cb + ci, gt = t0 + t - PAD;
        bool p = (gci < CI) && ((unsigned)gt < (unsigned)TLEN);
        const float* src = p ? (Xb + (size_t)gci * TLEN + gt) : Xb;
        cp_async4(XsBuf + ci * XR + t, src, p);
    }
    for (int i = tid; i < 8 * K * BM; i += 256) {
        int ci = i / (K * BM);
        int r  = i % (K * BM);
        int k = r / BM, o = r % BM;
        int gci = cb + ci, go = o0 + o;
        bool p = (gci < CI) && (go < CO);
        const float* src = p ? (Wp + ((size_t)gci * K + k) * CO + go) : Wp;
        cp_async4(WsBuf + i, src, p);
    }
}

template <int K>
__global__ void __launch_bounds__(256, 2)
conv_f2_kernel(const float* __restrict__ X, const float* __restrict__ Wp,
               const float* __restrict__ bias, float* __restrict__ Y,
               int CI, int CBx, int CO, int doStats) {
    const int BM = 128, BN = 128, BK = 8;
    const int XR = BN + (K - 1);
    const int NX = 8 + K - 1;
    const int XSZ = BK * XR;
    const int WSZ = BK * K * BM;

    extern __shared__ float sm[];
    float* Xs0 = sm;
    float* Ws0 = sm + 2 * XSZ;
    float* red = Ws0 + 2 * WSZ;

    int b  = blockIdx.z;
    int t0 = blockIdx.x * BN;
    int o0 = blockIdx.y * BM;
    int tid = threadIdx.x;
    int warp = tid >> 5, lane = tid & 31;
    int wco = warp & 1, wt = warp >> 1;
    int lco = lane >> 2, lt = lane & 3;
    int tco = wco * 64 + lco * 8;
    int tt  = wt * 32 + lt * 8;

    const float* Xb = X + (size_t)b * CBx * TLEN;
    int nchunk = (CI + BK - 1) / BK;

    u64 acc[4][8];
#pragma unroll
    for (int p = 0; p < 4; p++)
#pragma unroll
        for (int j = 0; j < 8; j++) acc[p][j] = 0ull;

    stage_tiles<K>(Xb, Wp, Xs0, Ws0, 0, CI, CO, t0, o0, tid);
    CP_COMMIT();

    for (int c = 0; c < nchunk; c++) {
        int buf = c & 1;
        if (c + 1 < nchunk) {
            stage_tiles<K>(Xb, Wp, Xs0 + (buf ^ 1) * XSZ, Ws0 + (buf ^ 1) * WSZ,
                           (c + 1) * BK, CI, CO, t0, o0, tid);
            CP_COMMIT();
            CP_WAIT(1);
        } else {
            CP_WAIT(0);
        }
        __syncthreads();

        const float* Xsb = Xs0 + buf * XSZ;
        const float* Wsb = Ws0 + buf * WSZ;
#pragma unroll
        for (int ci = 0; ci < BK; ci++) {
            u64 xs[NX];
#pragma unroll
            for (int v4 = 0; v4 < (NX + 3) / 4; v4++) {
                float4 xv = *(const float4*)&Xsb[ci * XR + tt + v4 * 4];
                if (v4 * 4 + 0 < NX) { u64 r; asm("mov.b64 %0,{%1,%1};":"=l"(r):"f"(xv.x)); xs[v4*4+0]=r; }
                if (v4 * 4 + 1 < NX) { u64 r; asm("mov.b64 %0,{%1,%1};":"=l"(r):"f"(xv.y)); xs[v4*4+1]=r; }
                if (v4 * 4 + 2 < NX) { u64 r; asm("mov.b64 %0,{%1,%1};":"=l"(r):"f"(xv.z)); xs[v4*4+2]=r; }
                if (v4 * 4 + 3 < NX) { u64 r; asm("mov.b64 %0,{%1,%1};":"=l"(r):"f"(xv.w)); xs[v4*4+3]=r; }
            }
#pragma unroll
            for (int k = 0; k < K; k++) {
                const float* wrow = Wsb + (ci * K + k) * BM + tco;
                ulonglong2 wa = *(const ulonglong2*)(wrow);
                ulonglong2 wb = *(const ulonglong2*)(wrow + 4);
                u64 wp[4] = {wa.x, wa.y, wb.x, wb.y};
#pragma unroll
                for (int p = 0; p < 4; p++)
#pragma unroll
                    for (int j = 0; j < 8; j++)
                        acc[p][j] = ffma2(wp[p], xs[j + k], acc[p][j]);
            }
        }
        __syncthreads();
    }

    int gt = t0 + tt;
    float ssum = 0.f, ssq = 0.f;
#pragma unroll
    for (int p = 0; p < 4; p++) {
        int oa = o0 + tco + 2 * p;
        int ob = oa + 1;
        bool va = oa < CO, vb = ob < CO;
        float ba = va ? bias[oa] : 0.f;
        float bb = vb ? bias[ob] : 0.f;
        float fa[8], fb[8];
#pragma unroll
        for (int j = 0; j < 8; j++) {
            float2 v = unpack2(acc[p][j]);
            fa[j] = v.x + ba; fb[j] = v.y + bb;
            if (va) { ssum += fa[j]; ssq += fa[j] * fa[j]; }
            if (vb) { ssum += fb[j]; ssq += fb[j] * fb[j]; }
        }
        if (va) {
            float* rowa = Y + ((size_t)b * CO + oa) * TLEN + gt;
            *(float4*)(rowa)     = make_float4(fa[0], fa[1], fa[2], fa[3]);
            *(float4*)(rowa + 4) = make_float4(fa[4], fa[5], fa[6], fa[7]);
        }
        if (vb) {
            float* rowb = Y + ((size_t)b * CO + ob) * TLEN + gt;
            *(float4*)(rowb)     = make_float4(fb[0], fb[1], fb[2], fb[3]);
            *(float4*)(rowb + 4) = make_float4(fb[4], fb[5], fb[6], fb[7]);
        }
    }
    if (doStats) {
#pragma unroll
        for (int off = 16; off > 0; off >>= 1) {
            ssum += __shfl_down_sync(0xffffffffu, ssum, off);
            ssq  += __shfl_down_sync(0xffffffffu, ssq,  off);
        }
        if (lane == 0) { red[warp] = ssum; red[8 + warp] = ssq; }
        __syncthreads();
        if (tid == 0) {
            double s = 0.0, s2 = 0.0;
            for (int w = 0; w < 8; w++) { s += red[w]; s2 += red[8 + w]; }
            atomicAdd(&g_stats[2 * b],     s);
            atomicAdd(&g_stats[2 * b + 1], s2);
        }
    }
}

__global__ void gn_lrelu_kernel(float* __restrict__ X,
                                const float* __restrict__ g,
                                const float* __restrict__ bt, int C) {
    int b = blockIdx.z, c = blockIdx.y;
    int t = blockIdx.x * 256 + threadIdx.x;
    double N = (double)C * TLEN;
    double mean = g_stats[2 * b] / N;
    double var  = g_stats[2 * b + 1] / N - mean * mean;
    float rstd = (float)rsqrt(var + GN_EPS);
    float sc = g[c] * rstd;
    float sh = bt[c] - (float)mean * sc;
    size_t idx = ((size_t)b * C + c) * TLEN + t;
    float yv = X[idx] * sc + sh;
    X[idx] = yv >= 0.f ? yv : LRELU_SLOPE * yv;
}

// GN+LReLU on [B][C][T] -> transpose -> fp16 split [m][C]
__global__ void gn_lrelu_t_split2(const float* __restrict__ X,
                                  const float* __restrict__ g,
                                  const float* __restrict__ bt, int C,
                                  u16* __restrict__ H, u16* __restrict__ L) {
    __shared__ float tile[32][33];
    int b = blockIdx.z;
    int c0 = blockIdx.y * 32, t0 = blockIdx.x * 32;
    double N = (double)C * 2048.0;
    double mean = g_stats[2 * b] / N;
    double var  = g_stats[2 * b + 1] / N - mean * mean;
    float rstd = (float)rsqrt(var + GN_EPS);
    float mf = (float)mean;
#pragma unroll
    for (int i = 0; i < 4; i++) {
        int c = c0 + threadIdx.y + i * 8;
        float sc = g[c] * rstd;
        float sh = bt[c] - mf * sc;
        float v = X[((size_t)b * C + c) * TLEN + t0 + threadIdx.x] * sc + sh;
        tile[threadIdx.y + i * 8][threadIdx.x] = v >= 0.f ? v : LRELU_SLOPE * v;
    }
    __syncthreads();
#pragma unroll
    for (int i = 0; i < 4; i++) {
        int lt = threadIdx.y + i * 8;
        int m = b * TLEN + t0 + lt;
        int c = c0 + threadIdx.x;
        split2h(tile[threadIdx.x][lt], H, L, (size_t)m * C + c);
    }
}

// GN+LReLU on [m][C] fp32 -> fp16 split [m][C]
__global__ void gn_lrelu_split2(const float* __restrict__ X,
                                const float* __restrict__ g,
                                const float* __restrict__ bt, int C,
                                u16* __restrict__ H, u16* __restrict__ L) {
    int m = blockIdx.y;
    int c = blockIdx.x * 256 + threadIdx.x;
    int b = m >> 11;
    double N = (double)C * TLEN;
    double mean = g_stats[2 * b] / N;
    double var  = g_stats[2 * b + 1] / N - mean * mean;
    float rstd = (float)rsqrt(var + GN_EPS);
    float sc = g[c] * rstd;
    float sh = bt[c] - (float)mean * sc;
    float yv = X[(size_t)m * C + c] * sc + sh;
    yv = yv >= 0.f ? yv : LRELU_SLOPE * yv;
    split2h(yv, H, L, (size_t)m * C + c);
}

// VQ on [B][128][T] z (proven); emits split2 zq into cat[m][128..255]
__global__ void vq_kernel(const float* __restrict__ z,
                          const float* __restrict__ cbn,
                          u16* __restrict__ catH, u16* __restrict__ catL) {
    __shared__ float zs[8][128];
    int warp = threadIdx.x >> 5, lane = threadIdx.x & 31;
    int pos = blockIdx.x * 8 + warp;
    int b = pos / TLEN, t = pos % TLEN;

    for (int d = lane; d < 128; d += 32)
        zs[warp][d] = z[((size_t)b * 128 + d) * TLEN + t];
    __syncwarp();

    const float4* zs4 = (const float4*)zs[warp];
    float best = -1e30f;
    int bk = 0;
    for (int kk = 0; kk < 16; kk++) {
        int k = kk * 32 + lane;
        const float4* cb4 = (const float4*)(cbn + (size_t)k * 128);
        float s = 0.f;
#pragma unroll
        for (int d4 = 0; d4 < 32; d4++) {
            float4 zv = zs4[d4], cv = cb4[d4];
            s += zv.x * cv.x + zv.y * cv.y + zv.z * cv.z + zv.w * cv.w;
        }
        if (s > best || (s == best && k < bk)) { best = s; bk = k; }
    }
    for (int off = 16; off > 0; off >>= 1) {
        float ob = __shfl_down_sync(0xffffffff, best, off);
        int   ok = __shfl_down_sync(0xffffffff, bk,   off);
        if (ob > best || (ob == best && ok < bk)) { best = ob; bk = ok; }
    }
    bk = __shfl_sync(0xffffffff, bk, 0);
    for (int d = lane; d < 128; d += 32)
        split2h(cbn[(size_t)bk * 128 + d], catH, catL,
                (size_t)pos * 640 + 128 + d);
}

// ================= fp16-split2 mma.sync GEMM (3 products) ================
// MODE 0: Y[m][CO] fp32.  MODE 2: Y[b][CO][t].
template <int MODE>
__global__ void __launch_bounds__(256)
gemm_mma_kernel(const u16* __restrict__ AH, const u16* __restrict__ AL,
                const u16* __restrict__ WH, const u16* __restrict__ WL,
                const float* __restrict__ bias, float* __restrict__ Y,
                int RS, int CS, int K, int CO, int doStats) {
    const int BUFB = 4 * 16384;
    extern __shared__ char dsm[];
    __shared__ float s_bias[128];
    __shared__ float s_red[16];

    const int PAD = (K - 1) / 2;
    const int KP = K * CS;
    const int cs64 = CS >> 6;
    const int nch = K * cs64;

    int tid = threadIdx.x, wid = tid >> 5, lane = tid & 31;
    int co0 = blockIdx.x * 128, m0 = blockIdx.y * 128;
    u32 sb = smem_u32(dsm);

    auto stage = [&](int c, int buf) {
        int k = c / cs64;
        int cib = (c - k * cs64) << 6;
        int dk = k - PAD;
        u32 base = sb + buf * BUFB;
        for (int i = tid; i < 1024; i += 256) {
            int r = i >> 3, g7 = i & 7;
            u32 soff = SW128(r * 128 + g7 * 16);
            int m = m0 + r;
            int tt = (m & 2047) + dk;
            bool pv = (unsigned)tt < 2048u;
            size_t aoff = (size_t)(m + dk) * RS + cib + g7 * 8;
            cp_async16(base + soff, pv ? AH + aoff : AH, pv);
            cp_async16(base + 16384 + soff, pv ? AL + aoff : AL, pv);
            int co = co0 + r;
            bool pw = co < CO;
            size_t woff = (size_t)co * KP + c * 64 + g7 * 8;
            cp_async16(base + 32768 + soff, pw ? WH + woff : WH, pw);
            cp_async16(base + 49152 + soff, pw ? WL + woff : WL, pw);
        }
        CP_COMMIT();
    };

    float acc[2][8][4];
#pragma unroll
    for (int a = 0; a < 2; a++)
#pragma unroll
        for (int b = 0; b < 8; b++)
#pragma unroll
            for (int c = 0; c < 4; c++) acc[a][b][c] = 0.f;

    int wm = (wid & 3) * 32, wn = (wid >> 2) * 64;
    int quad = lane >> 3, l7 = lane & 7;
    int arow = wm + (quad & 1) * 8 + l7;
    int acolb = (quad >> 1) * 16;
    int brow = wn + (quad >> 1) * 8 + l7;
    int bcolb = (quad & 1) * 16;

    stage(0, 0);
    if (nch > 1) stage(1, 1);

    for (int c = 0; c < nch; c++) {
        int buf = c % 3;
        if (c + 2 < nch) { stage(c + 2, (c + 2) % 3); CP_WAIT(2); }
        else if (c + 1 < nch) { CP_WAIT(1); }
        else { CP_WAIT(0); }
        __syncthreads();

        u32 baseA = sb + buf * BUFB;
        u32 baseW = baseA + 32768;
#pragma unroll
        for (int ks = 0; ks < 4; ks++) {
            u32 ah[2][4], al[2][4];
#pragma unroll
            for (int mt = 0; mt < 2; mt++) {
                u32 off = SW128((arow + mt * 16) * 128 + acolb + ks * 32);
                ldsm4(ah[mt], baseA + off);
                ldsm4(al[mt], baseA + 16384 + off);
            }
#pragma unroll
            for (int nt2 = 0; nt2 < 4; nt2++) {
                u32 off = SW128((brow + nt2 * 16) * 128 + bcolb + ks * 32);
                u32 bh[4], bl[4];
                ldsm4(bh, baseW + off);
                ldsm4(bl, baseW + 16384 + off);
#pragma unroll
                for (int mt = 0; mt < 2; mt++) {
                    mma_f16(acc[mt][2 * nt2],     ah[mt], bh);
                    mma_f16(acc[mt][2 * nt2],     ah[mt], bl);
                    mma_f16(acc[mt][2 * nt2],     al[mt], bh);
                    mma_f16(acc[mt][2 * nt2 + 1], ah[mt], bh + 2);
                    mma_f16(acc[mt][2 * nt2 + 1], ah[mt], bl + 2);
                    mma_f16(acc[mt][2 * nt2 + 1], al[mt], bh + 2);
                }
            }
        }
        __syncthreads();
    }

    if (tid < 128) {
        int co = co0 + tid;
        s_bias[tid] = (co < CO) ? bias[co] : 0.f;
    }
    __syncthreads();

    int g = lane >> 2, tg = lane & 3;
    float ssum = 0.f, ssq = 0.f;
#pragma unroll
    for (int mt = 0; mt < 2; mt++) {
#pragma unroll
        for (int nt = 0; nt < 8; nt++) {
            int colb = wn + nt * 8 + tg * 2;
            float b0 = s_bias[colb], b1 = s_bias[colb + 1];
            float f00 = acc[mt][nt][0] + b0, f01 = acc[mt][nt][1] + b1;
            float f10 = acc[mt][nt][2] + b0, f11 = acc[mt][nt][3] + b1;
            int m1 = m0 + wm + mt * 16 + g;
            int co = co0 + colb;
            if (MODE == 0) {
                *(float2*)&Y[(size_t)m1 * CO + co] = make_float2(f00, f01);
                *(float2*)&Y[(size_t)(m1 + 8) * CO + co] = make_float2(f10, f11);
                ssum += f00 + f01 + f10 + f11;
                ssq += f00 * f00 + f01 * f01 + f10 * f10 + f11 * f11;
            } else {
                int b = m1 >> 11, t = m1 & 2047;
                if (co < CO) {
                    Y[((size_t)b * CO + co) * TLEN + t] = f00;
                    Y[((size_t)b * CO + co) * TLEN + t + 8] = f10;
                    ssum += f00 + f10; ssq += f00 * f00 + f10 * f10;
                }
                if (co + 1 < CO) {
                    Y[((size_t)b * CO + co + 1) * TLEN + t] = f01;
                    Y[((size_t)b * CO + co + 1) * TLEN + t + 8] = f11;
                    ssum += f01 + f11; ssq += f01 * f01 + f11 * f11;
                }
            }
        }
    }

    if (doStats) {
#pragma unroll
        for (int off = 16; off > 0; off >>= 1) {
            ssum += __shfl_down_sync(0xffffffffu, ssum, off);
            ssq  += __shfl_down_sync(0xffffffffu, ssq,  off);
        }
        if (lane == 0) { s_red[wid] = ssum; s_red[8 + wid] = ssq; }
        __syncthreads();
        if (tid == 0) {
            double s = 0.0, s2 = 0.0;
            for (int w = 0; w < 8; w++) { s += s_red[w]; s2 += s_red[8 + w]; }
            int b = m0 >> 11;
            atomicAdd(&g_stats[2 * b], s);
            atomicAdd(&g_stats[2 * b + 1], s2);
        }
    }
}

__global__ void gn_glu_split2(const float* __restrict__ X,
                              const float* __restrict__ g,
                              const float* __restrict__ bt,
                              u16* __restrict__ catH, u16* __restrict__ catL) {
    int m = blockIdx.y;
    int c = blockIdx.x * 256 + threadIdx.x;  // < 512
    int b = m >> 11;
    double N = 1024.0 * TLEN;
    double mean = g_stats[2 * b] / N;
    double var  = g_stats[2 * b + 1] / N - mean * mean;
    float rstd = (float)rsqrt(var + GN_EPS);
    float mf = (float)mean;
    float a  = X[(size_t)m * 1024 + c];
    float gv = X[(size_t)m * 1024 + 512 + c];
    float na = (a  - mf) * rstd * g[c]       + bt[c];
    float ng = (gv - mf) * rstd * g[c + 512] + bt[c + 512];
    float v = na / (1.f + expf(-ng));
    split2h(v, catH, catL, (size_t)m * 640 + 128 + c);
}

// ---------------- host ----------------
static const int SMEM_K5 = (2 * (8 * 132) + 2 * (8 * 5 * 128) + 16) * 4;
static const int SMEM_G  = 3 * 4 * 16384;  // 196608

static void launch_conv(const float* X, const float* Wp, const float* b,
                        float* Y, int CI, int CBx, int CO, int doStats) {
    dim3 grid(TLEN / 128, (CO + 127) / 128, BATCH);
    if (doStats) zero_stats_kernel<<<1, 32>>>();
    conv_f2_kernel<5><<<grid, 256, SMEM_K5>>>(X, Wp, b, Y, CI, CBx, CO, doStats);
}

extern "C" void kernel_launch(void* const* d_in, const int* in_sizes, int n_in,
                              void* d_out, int out_size) {
    const float* x    = (const float*)d_in[0];
    const int*   y    = (const int*)  d_in[1];
    const float* spk  = (const float*)d_in[2];
    const float* cb   = (const float*)d_in[3];
    const float *ew0 = (const float*)d_in[4],  *eb0 = (const float*)d_in[5];
    const float *eg0 = (const float*)d_in[6],  *et0 = (const float*)d_in[7];
    const float *ew1 = (const float*)d_in[8],  *eb1 = (const float*)d_in[9];
    const float *eg1 = (const float*)d_in[10], *et1 = (const float*)d_in[11];
    const float *ew2 = (const float*)d_in[12], *eb2 = (const float*)d_in[13];
    const float *eg2 = (const float*)d_in[14], *et2 = (const float*)d_in[15];
    const float *mw  = (const float*)d_in[16], *mb  = (const float*)d_in[17];
    const float *dw0 = (const float*)d_in[18], *db0 = (const float*)d_in[19];
    const float *dg0 = (const float*)d_in[20], *dt0 = (const float*)d_in[21];
    const float *dw1 = (const float*)d_in[22], *db1 = (const float*)d_in[23];
    const float *dg1 = (const float*)d_in[24], *dt1 = (const float*)d_in[25];
    const float *dw2 = (const float*)d_in[26], *db2 = (const float*)d_in[27];
    float* out = (float*)d_out;

    cudaFuncSetAttribute(conv_f2_kernel<5>,
                         cudaFuncAttributeMaxDynamicSharedMemorySize, SMEM_K5);
    cudaFuncSetAttribute(gemm_mma_kernel<0>,
                         cudaFuncAttributeMaxDynamicSharedMemorySize, SMEM_G);
    cudaFuncSetAttribute(gemm_mma_kernel<2>,
                         cudaFuncAttributeMaxDynamicSharedMemorySize, SMEM_G);

    float *bufA, *bufB, *z, *spkn, *cbn, *we0, *we1;
    u16 *aH, *aL, *bH, *bL, *catH, *catL;
    u16 *w2h, *w2l, *wmh, *wml;
    u16 *d0h, *d0l, *d1h, *d1l, *d2h, *d2l;
    cudaGetSymbolAddress((void**)&bufA, g_bufA);
    cudaGetSymbolAddress((void**)&bufB, g_bufB);
    cudaGetSymbolAddress((void**)&z,    g_z);
    cudaGetSymbolAddress((void**)&spkn, g_spkn);
    cudaGetSymbolAddress((void**)&cbn,  g_cbn);
    cudaGetSymbolAddress((void**)&we0,  g_we0);
    cudaGetSymbolAddress((void**)&we1,  g_we1);
    cudaGetSymbolAddress((void**)&aH,   g_aH);
    cudaGetSymbolAddress((void**)&aL,   g_aL);
    cudaGetSymbolAddress((void**)&bH,   g_bH);
    cudaGetSymbolAddress((void**)&bL,   g_bL);
    cudaGetSymbolAddress((void**)&catH, g_catH);
    cudaGetSymbolAddress((void**)&catL, g_catL);
    cudaGetSymbolAddress((void**)&w2h,  g_w2h);
    cudaGetSymbolAddress((void**)&w2l,  g_w2l);
    cudaGetSymbolAddress((void**)&wmh,  g_wmh);
    cudaGetSymbolAddress((void**)&wml,  g_wml);
    cudaGetSymbolAddress((void**)&d0h, g_d0h); cudaGetSymbolAddress((void**)&d0l, g_d0l);
    cudaGetSymbolAddress((void**)&d1h, g_d1h); cudaGetSymbolAddress((void**)&d1l, g_d1l);
    cudaGetSymbolAddress((void**)&d2h, g_d2h); cudaGetSymbolAddress((void**)&d2l, g_d2l);

    // ---- prep ----
    normalize_rows_kernel<<<64, 128>>>(spk, spkn);
    normalize_rows_kernel<<<512, 128>>>(cb, cbn);
    gather_yv_kernel<<<MTOT, 128>>>(y, spkn, catH, catL);
    wenc_kernel<<<(1024 * 39 * 5 + 255) / 256, 256>>>(ew0, we0, 39, 1024, 5);
    wenc_kernel<<<(512 * 1024 * 5 + 255) / 256, 256>>>(ew1, we1, 1024, 512, 5);
    wsplit_enc_h<<<(512 * 2560 + 255) / 256, 256>>>(ew2, w2h, w2l, 512, 512, 512, 5);
    wsplit_enc_h<<<(128 * 512 + 255) / 256, 256>>>(mw, wmh, wml, 512, 512, 128, 1);
    wsplit_dec<<<(1024 * 1280 + 255) / 256, 256>>>(dw0, d0h, d0l, 256, 1024, 128);
    wsplit_dec<<<(1024 * 3200 + 255) / 256, 256>>>(dw1, d1h, d1l, 640, 1024, 512);
    wsplit_dec<<<(39 * 3200 + 255) / 256, 256>>>(dw2, d2h, d2l, 640, 39, 512);

    // ---- enc L0, L1 (proven FFMA2, [B][C][T]) ----
    launch_conv(x, we0, eb0, bufA, 39, 39, 1024, 1);
    gn_lrelu_kernel<<<dim3(TLEN / 256, 1024, BATCH), 256>>>(bufA, eg0, et0, 1024);

    launch_conv(bufA, we1, eb1, bufB, 1024, 1024, 512, 1);
    // GN + transpose -> split [m][512]
    gn_lrelu_t_split2<<<dim3(TLEN / 32, 512 / 32, BATCH), dim3(32, 8)>>>(
        bufB, eg1, et1, 512, aH, aL);

    // ---- enc L2 (mma gemm CS=512, MODE 0, +stats) — UNDER TEST ----
    zero_stats_kernel<<<1, 32>>>();
    gemm_mma_kernel<0><<<dim3(4, MTOT / 128), 256, SMEM_G>>>(
        aH, aL, w2h, w2l, eb2, bufA, 512, 512, 5, 512, 1);
    gn_lrelu_split2<<<dim3(2, MTOT), 256>>>(bufA, eg2, et2, 512, bH, bL);

    // ---- 1x1 (mma gemm K=1, MODE 2 -> z [B][128][T]) — UNDER TEST ----
    gemm_mma_kernel<2><<<dim3(1, MTOT / 128), 256, SMEM_G>>>(
        bH, bL, wmh, wml, mb, z, 512, 512, 1, 128, 0);

    // ---- VQ -> cat[m][128..255] split2 ----
    vq_kernel<<<MTOT / 8, 256>>>(z, cbn, catH, catL);

    // ---- decoder (proven fp16-split2 mma GEMM) ----
    zero_stats_kernel<<<1, 32>>>();
    gemm_mma_kernel<0><<<dim3(8, MTOT / 128), 256, SMEM_G>>>(
        catH, catL, d0h, d0l, db0, bufA, 640, 256, 5, 1024, 1);
    gn_glu_split2<<<dim3(2, MTOT), 256>>>(bufA, dg0, dt0, catH, catL);

    zero_stats_kernel<<<1, 32>>>();
    gemm_mma_kernel<0><<<dim3(8, MTOT / 128), 256, SMEM_G>>>(
        catH, catL, d1h, d1l, db1, bufA, 640, 640, 5, 1024, 1);
    gn_glu_split2<<<dim3(2, MTOT), 256>>>(bufA, dg1, dt1, catH, catL);

    gemm_mma_kernel<2><<<dim3(1, MTOT / 128), 256, SMEM_G>>>(
        catH, catL, d2h, d2l, db2, out, 640, 640, 5, 39, 0);
}

// round 15
// speedup vs baseline: 2.7434x; 1.2947x over previous
#include <cuda_runtime.h>
#include <cuda_fp16.h>
#include <math.h>
#include <stdint.h>

#define BATCH 16
#define TLEN  2048
#define MTOT  (BATCH * TLEN)
#define LRELU_SLOPE 0.02f
#define GN_EPS 1e-5

typedef unsigned long long u64;
typedef unsigned int u32;
typedef unsigned short u16;

// ---------------- scratch ----------------
__device__ float g_bufA[(size_t)MTOT * 1024];
__device__ float g_z   [(size_t)MTOT * 128];      // [B][128][T]
__device__ float g_spkn[64 * 128];
__device__ float g_cbn [512 * 128];
__device__ float g_zbias[1024];                   // zero bias (static init 0)
__device__ u16   g_aH[(size_t)MTOT * 512],  g_aL[(size_t)MTOT * 512];
__device__ u16   g_a2H[(size_t)MTOT * 512], g_a2L[(size_t)MTOT * 512];
__device__ u16   g_bH[(size_t)MTOT * 512],  g_bL[(size_t)MTOT * 512];
__device__ u16   g_catH[(size_t)MTOT * 640], g_catL[(size_t)MTOT * 640];
__device__ float g_we0[39 * 5 * 1024];
__device__ u16 g_w1ah[512 * 2560], g_w1al[512 * 2560];
__device__ u16 g_w1bh[512 * 2560], g_w1bl[512 * 2560];
__device__ u16 g_w2h[512 * 2560],  g_w2l[512 * 2560];
__device__ u16 g_wmh[128 * 512],   g_wml[128 * 512];
__device__ u16 g_d0h[1024 * 1280], g_d0l[1024 * 1280];
__device__ u16 g_d1h[1024 * 3200], g_d1l[1024 * 3200];
__device__ u16 g_d2h[39 * 3200],   g_d2l[39 * 3200];
__device__ double g_stats[2 * BATCH];

// ---------------- common helpers ----------------
__device__ __forceinline__ u64 ffma2(u64 a, u64 b, u64 c) {
    u64 d; asm("fma.rn.f32x2 %0, %1, %2, %3;" : "=l"(d) : "l"(a), "l"(b), "l"(c));
    return d;
}
__device__ __forceinline__ float2 unpack2(u64 v) {
    float2 f; asm("mov.b64 {%0, %1}, %2;" : "=f"(f.x), "=f"(f.y) : "l"(v));
    return f;
}
__device__ __forceinline__ void cp_async4(void* smem, const float* g, bool p) {
    unsigned s = (unsigned)__cvta_generic_to_shared(smem);
    int sz = p ? 4 : 0;
    asm volatile("cp.async.ca.shared.global [%0], [%1], 4, %2;"
                 :: "r"(s), "l"(g), "r"(sz));
}
__device__ __forceinline__ u32 smem_u32(const void* p) {
    u32 a;
    asm("{ .reg .u64 t; cvta.to.shared.u64 t, %1; cvt.u32.u64 %0, t; }"
        : "=r"(a) : "l"(p));
    return a;
}
__device__ __forceinline__ void cp_async16(u32 saddr, const void* g, bool p) {
    int sz = p ? 16 : 0;
    asm volatile("cp.async.cg.shared.global [%0], [%1], 16, %2;"
                 :: "r"(saddr), "l"(g), "r"(sz));
}
#define CP_COMMIT() asm volatile("cp.async.commit_group;" ::: "memory")
#define CP_WAIT(n)  asm volatile("cp.async.wait_group %0;" :: "n"(n) : "memory")
#define SW128(o) ((u32)(o) ^ ((((u32)(o)) >> 3) & 0x70u))

__device__ __forceinline__ void ldsm4(u32* r, u32 addr) {
    asm volatile("ldmatrix.sync.aligned.m8n8.x4.shared.b16 {%0,%1,%2,%3}, [%4];"
                 : "=r"(r[0]), "=r"(r[1]), "=r"(r[2]), "=r"(r[3]) : "r"(addr));
}
__device__ __forceinline__ void mma_f16(float* d, const u32* a, const u32* b) {
    asm volatile(
        "mma.sync.aligned.m16n8k16.row.col.f32.f16.f16.f32 "
        "{%0,%1,%2,%3},{%4,%5,%6,%7},{%8,%9},{%0,%1,%2,%3};"
        : "+f"(d[0]), "+f"(d[1]), "+f"(d[2]), "+f"(d[3])
        : "r"(a[0]), "r"(a[1]), "r"(a[2]), "r"(a[3]), "r"(b[0]), "r"(b[1]));
}
__device__ __forceinline__ void split2h(float v, u16* H, u16* L, size_t i) {
    __half h = __float2half_rn(v);
    float r = v - __half2float(h);
    __half l = __float2half_rn(r);
    H[i] = *(u16*)&h; L[i] = *(u16*)&l;
}

// ---------------- prep kernels ----------------
__global__ void normalize_rows_kernel(const float* __restrict__ in,
                                      float* __restrict__ out) {
    int r = blockIdx.x, tid = threadIdx.x;
    float v = in[r * 128 + tid];
    __shared__ float sh[128];
    sh[tid] = v * v;
    __syncthreads();
    for (int off = 64; off > 0; off >>= 1) {
        if (tid < off) sh[tid] += sh[tid + off];
        __syncthreads();
    }
    out[r * 128 + tid] = v * rsqrtf(sh[0] + 1e-12f);
}

__global__ void zero_bias_kernel() {
    int i = blockIdx.x * 256 + threadIdx.x;
    if (i < 1024) g_zbias[i] = 0.f;
}

__global__ void wenc_kernel(const float* __restrict__ W, float* __restrict__ Wp,
                            int CI, int CO, int K) {
    int idx = blockIdx.x * 256 + threadIdx.x;
    if (idx >= CO * CI * K) return;
    int k  = idx % K;
    int ci = (idx / K) % CI;
    int co = idx / (K * CI);
    Wp[((size_t)ci * K + k) * CO + co] = W[idx];
}

__global__ void wsplit_enc_h(const float* __restrict__ W, u16* Wh, u16* Wl,
                             int CI, int CS, int CO, int K, int cib0) {
    int i = blockIdx.x * 256 + threadIdx.x;
    if (i >= CO * K * CS) return;
    int co = i / (K * CS), j = i % (K * CS);
    int k = j / CS, ci = cib0 + j % CS;
    float v = (ci < CI) ? W[((size_t)co * CI + ci) * K + k] : 0.f;
    split2h(v, Wh, Wl, i);
}

__global__ void wsplit_dec(const float* __restrict__ W, u16* Wh, u16* Wl,
                           int CS, int CO, int split) {
    int i = blockIdx.x * 256 + threadIdx.x;
    if (i >= CO * 5 * CS) return;
    int co = i / (5 * CS), j = i % (5 * CS);
    int k = j / CS, ci = j % CS;
    int ci0 = (ci < 128) ? ci + split : ci - 128;
    float v = W[((size_t)ci0 * CO + co) * 5 + (4 - k)];
    split2h(v, Wh, Wl, i);
}

__global__ void gather_yv_kernel(const int* __restrict__ y,
                                 const float* __restrict__ spkn,
                                 u16* __restrict__ H, u16* __restrict__ L) {
    int m = blockIdx.x;
    int idx = y[m];
    split2h(spkn[idx * 128 + threadIdx.x], H, L, (size_t)m * 640 + threadIdx.x);
}

__global__ void zero_stats_kernel() {
    if (threadIdx.x < 2 * BATCH) g_stats[threadIdx.x] = 0.0;
}

// ================= FFMA2 encoder conv ([B][C][T]) — proven ===============
template <int K>
__device__ __forceinline__ void stage_tiles(
    const float* __restrict__ Xb, const float* __restrict__ Wp,
    float* XsBuf, float* WsBuf, int cb, int CI, int CO, int t0, int o0, int tid) {
    const int BM = 128, XR = 128 + (K - 1), PAD = (K - 1) / 2;
    for (int i = tid; i < 8 * XR; i += 256) {
        int ci = i / XR, t = i % XR;
        int gci = cb + ci, gt = t0 + t - PAD;
        bool p = (gci < CI) && ((unsigned)gt < (unsigned)TLEN);
        const float* src = p ? (Xb + (size_t)gci * TLEN + gt) : Xb;
        cp_async4(XsBuf + ci * XR + t, src, p);
    }
    for (int i = tid; i < 8 * K * BM; i += 256) {
        int ci = i / (K * BM);
        int r  = i % (K * BM);
        int k = r / BM, o = r % BM;
        int gci = cb + ci, go = o0 + o;
        bool p = (gci < CI) && (go < CO);
        const float* src = p ? (Wp + ((size_t)gci * K + k) * CO + go) : Wp;
        cp_async4(WsBuf + i, src, p);
    }
}

template <int K>
__global__ void __launch_bounds__(256, 2)
conv_f2_kernel(const float* __restrict__ X, const float* __restrict__ Wp,
               const float* __restrict__ bias, float* __restrict__ Y,
               int CI, int CBx, int CO, int doStats) {
    const int BM = 128, BN = 128, BK = 8;
    const int XR = BN + (K - 1);
    const int NX = 8 + K - 1;
    const int XSZ = BK * XR;
    const int WSZ = BK * K * BM;

    extern __shared__ float sm[];
    float* Xs0 = sm;
    float* Ws0 = sm + 2 * XSZ;
    float* red = Ws0 + 2 * WSZ;

    int b  = blockIdx.z;
    int t0 = blockIdx.x * BN;
    int o0 = blockIdx.y * BM;
    int tid = threadIdx.x;
    int warp = tid >> 5, lane = tid & 31;
    int wco = warp & 1, wt = warp >> 1;
    int lco = lane >> 2, lt = lane & 3;
    int tco = wco * 64 + lco * 8;
    int tt  = wt * 32 + lt * 8;

    const float* Xb = X + (size_t)b * CBx * TLEN;
    int nchunk = (CI + BK - 1) / BK;

    u64 acc[4][8];
#pragma unroll
    for (int p = 0; p < 4; p++)
#pragma unroll
        for (int j = 0; j < 8; j++) acc[p][j] = 0ull;

    stage_tiles<K>(Xb, Wp, Xs0, Ws0, 0, CI, CO, t0, o0, tid);
    CP_COMMIT();

    for (int c = 0; c < nchunk; c++) {
        int buf = c & 1;
        if (c + 1 < nchunk) {
            stage_tiles<K>(Xb, Wp, Xs0 + (buf ^ 1) * XSZ, Ws0 + (buf ^ 1) * WSZ,
                           (c + 1) * BK, CI, CO, t0, o0, tid);
            CP_COMMIT();
            CP_WAIT(1);
        } else {
            CP_WAIT(0);
        }
        __syncthreads();

        const float* Xsb = Xs0 + buf * XSZ;
        const float* Wsb = Ws0 + buf * WSZ;
#pragma unroll
        for (int ci = 0; ci < BK; ci++) {
            u64 xs[NX];
#pragma unroll
            for (int v4 = 0; v4 < (NX + 3) / 4; v4++) {
                float4 xv = *(const float4*)&Xsb[ci * XR + tt + v4 * 4];
                if (v4 * 4 + 0 < NX) { u64 r; asm("mov.b64 %0,{%1,%1};":"=l"(r):"f"(xv.x)); xs[v4*4+0]=r; }
                if (v4 * 4 + 1 < NX) { u64 r; asm("mov.b64 %0,{%1,%1};":"=l"(r):"f"(xv.y)); xs[v4*4+1]=r; }
                if (v4 * 4 + 2 < NX) { u64 r; asm("mov.b64 %0,{%1,%1};":"=l"(r):"f"(xv.z)); xs[v4*4+2]=r; }
                if (v4 * 4 + 3 < NX) { u64 r; asm("mov.b64 %0,{%1,%1};":"=l"(r):"f"(xv.w)); xs[v4*4+3]=r; }
            }
#pragma unroll
            for (int k = 0; k < K; k++) {
                const float* wrow = Wsb + (ci * K + k) * BM + tco;
                ulonglong2 wa = *(const ulonglong2*)(wrow);
                ulonglong2 wb = *(const ulonglong2*)(wrow + 4);
                u64 wp[4] = {wa.x, wa.y, wb.x, wb.y};
#pragma unroll
                for (int p = 0; p < 4; p++)
#pragma unroll
                    for (int j = 0; j < 8; j++)
                        acc[p][j] = ffma2(wp[p], xs[j + k], acc[p][j]);
            }
        }
        __syncthreads();
    }

    int gt = t0 + tt;
    float ssum = 0.f, ssq = 0.f;
#pragma unroll
    for (int p = 0; p < 4; p++) {
        int oa = o0 + tco + 2 * p;
        int ob = oa + 1;
        bool va = oa < CO, vb = ob < CO;
        float ba = va ? bias[oa] : 0.f;
        float bb = vb ? bias[ob] : 0.f;
        float fa[8], fb[8];
#pragma unroll
        for (int j = 0; j < 8; j++) {
            float2 v = unpack2(acc[p][j]);
            fa[j] = v.x + ba; fb[j] = v.y + bb;
            if (va) { ssum += fa[j]; ssq += fa[j] * fa[j]; }
            if (vb) { ssum += fb[j]; ssq += fb[j] * fb[j]; }
        }
        if (va) {
            float* rowa = Y + ((size_t)b * CO + oa) * TLEN + gt;
            *(float4*)(rowa)     = make_float4(fa[0], fa[1], fa[2], fa[3]);
            *(float4*)(rowa + 4) = make_float4(fa[4], fa[5], fa[6], fa[7]);
        }
        if (vb) {
            float* rowb = Y + ((size_t)b * CO + ob) * TLEN + gt;
            *(float4*)(rowb)     = make_float4(fb[0], fb[1], fb[2], fb[3]);
            *(float4*)(rowb + 4) = make_float4(fb[4], fb[5], fb[6], fb[7]);
        }
    }
    if (doStats) {
#pragma unroll
        for (int off = 16; off > 0; off >>= 1) {
            ssum += __shfl_down_sync(0xffffffffu, ssum, off);
            ssq  += __shfl_down_sync(0xffffffffu, ssq,  off);
        }
        if (lane == 0) { red[warp] = ssum; red[8 + warp] = ssq; }
        __syncthreads();
        if (tid == 0) {
            double s = 0.0, s2 = 0.0;
            for (int w = 0; w < 8; w++) { s += red[w]; s2 += red[8 + w]; }
            atomicAdd(&g_stats[2 * b],     s);
            atomicAdd(&g_stats[2 * b + 1], s2);
        }
    }
}

// GN+LReLU on [B][Cfull][T], transpose channels [cbase, cbase+Chalf) ->
// fp16 split [m][Chalf].
__global__ void gn_lrelu_t_split2(const float* __restrict__ X,
                                  const float* __restrict__ g,
                                  const float* __restrict__ bt,
                                  int Cfull, int cbase, int Chalf,
                                  u16* __restrict__ H, u16* __restrict__ L) {
    __shared__ float tile[32][33];
    int b = blockIdx.z;
    int cl0 = blockIdx.y * 32;
    int t0 = blockIdx.x * 32;
    double N = (double)Cfull * 2048.0;
    double mean = g_stats[2 * b] / N;
    double var  = g_stats[2 * b + 1] / N - mean * mean;
    float rstd = (float)rsqrt(var + GN_EPS);
    float mf = (float)mean;
#pragma unroll
    for (int i = 0; i < 4; i++) {
        int c = cbase + cl0 + threadIdx.y + i * 8;
        float sc = g[c] * rstd;
        float sh = bt[c] - mf * sc;
        float v = X[((size_t)b * Cfull + c) * TLEN + t0 + threadIdx.x] * sc + sh;
        tile[threadIdx.y + i * 8][threadIdx.x] = v >= 0.f ? v : LRELU_SLOPE * v;
    }
    __syncthreads();
#pragma unroll
    for (int i = 0; i < 4; i++) {
        int lt = threadIdx.y + i * 8;
        int m = b * TLEN + t0 + lt;
        int cl = cl0 + threadIdx.x;
        split2h(tile[threadIdx.x][lt], H, L, (size_t)m * Chalf + cl);
    }
}

__global__ void gn_lrelu_split2(const float* __restrict__ X,
                                const float* __restrict__ g,
                                const float* __restrict__ bt, int C,
                                u16* __restrict__ H, u16* __restrict__ L) {
    int m = blockIdx.y;
    int c = blockIdx.x * 256 + threadIdx.x;
    int b = m >> 11;
    double N = (double)C * TLEN;
    double mean = g_stats[2 * b] / N;
    double var  = g_stats[2 * b + 1] / N - mean * mean;
    float rstd = (float)rsqrt(var + GN_EPS);
    float sc = g[c] * rstd;
    float sh = bt[c] - (float)mean * sc;
    float yv = X[(size_t)m * C + c] * sc + sh;
    yv = yv >= 0.f ? yv : LRELU_SLOPE * yv;
    split2h(yv, H, L, (size_t)m * C + c);
}

__global__ void vq_kernel(const float* __restrict__ z,
                          const float* __restrict__ cbn,
                          u16* __restrict__ catH, u16* __restrict__ catL) {
    __shared__ float zs[8][128];
    int warp = threadIdx.x >> 5, lane = threadIdx.x & 31;
    int pos = blockIdx.x * 8 + warp;
    int b = pos / TLEN, t = pos % TLEN;

    for (int d = lane; d < 128; d += 32)
        zs[warp][d] = z[((size_t)b * 128 + d) * TLEN + t];
    __syncwarp();

    const float4* zs4 = (const float4*)zs[warp];
    float best = -1e30f;
    int bk = 0;
    for (int kk = 0; kk < 16; kk++) {
        int k = kk * 32 + lane;
        const float4* cb4 = (const float4*)(cbn + (size_t)k * 128);
        float s = 0.f;
#pragma unroll
        for (int d4 = 0; d4 < 32; d4++) {
            float4 zv = zs4[d4], cv = cb4[d4];
            s += zv.x * cv.x + zv.y * cv.y + zv.z * cv.z + zv.w * cv.w;
        }
        if (s > best || (s == best && k < bk)) { best = s; bk = k; }
    }
    for (int off = 16; off > 0; off >>= 1) {
        float ob = __shfl_down_sync(0xffffffff, best, off);
        int   ok = __shfl_down_sync(0xffffffff, bk,   off);
        if (ob > best || (ob == best && ok < bk)) { best = ob; bk = ok; }
    }
    bk = __shfl_sync(0xffffffff, bk, 0);
    for (int d = lane; d < 128; d += 32)
        split2h(cbn[(size_t)bk * 128 + d], catH, catL,
                (size_t)pos * 640 + 128 + d);
}

// ================= fp16-split2 mma.sync GEMM (3 products) ================
template <int MODE>
__global__ void __launch_bounds__(256)
gemm_mma_kernel(const u16* __restrict__ AH, const u16* __restrict__ AL,
                const u16* __restrict__ WH, const u16* __restrict__ WL,
                const float* __restrict__ bias, float* __restrict__ Y,
                int RS, int CS, int K, int CO, int doStats, int accum) {
    const int BUFB = 4 * 16384;
    extern __shared__ char dsm[];
    __shared__ float s_bias[128];
    __shared__ float s_red[16];

    const int PAD = (K - 1) / 2;
    const int KP = K * CS;
    const int cs64 = CS >> 6;
    const int nch = K * cs64;

    int tid = threadIdx.x, wid = tid >> 5, lane = tid & 31;
    int co0 = blockIdx.x * 128, m0 = blockIdx.y * 128;
    u32 sb = smem_u32(dsm);

    auto stage = [&](int c, int buf) {
        int k = c / cs64;
        int cib = (c - k * cs64) << 6;
        int dk = k - PAD;
        u32 base = sb + buf * BUFB;
        for (int i = tid; i < 1024; i += 256) {
            int r = i >> 3, g7 = i & 7;
            u32 soff = SW128(r * 128 + g7 * 16);
            int m = m0 + r;
            int tt = (m & 2047) + dk;
            bool pv = (unsigned)tt < 2048u;
            size_t aoff = (size_t)(m + dk) * RS + cib + g7 * 8;
            cp_async16(base + soff, pv ? AH + aoff : AH, pv);
            cp_async16(base + 16384 + soff, pv ? AL + aoff : AL, pv);
            int co = co0 + r;
            bool pw = co < CO;
            size_t woff = (size_t)co * KP + c * 64 + g7 * 8;
            cp_async16(base + 32768 + soff, pw ? WH + woff : WH, pw);
            cp_async16(base + 49152 + soff, pw ? WL + woff : WL, pw);
        }
        CP_COMMIT();
    };

    float acc[2][8][4];
#pragma unroll
    for (int a = 0; a < 2; a++)
#pragma unroll
        for (int b = 0; b < 8; b++)
#pragma unroll
            for (int c = 0; c < 4; c++) acc[a][b][c] = 0.f;

    int wm = (wid & 3) * 32, wn = (wid >> 2) * 64;
    int quad = lane >> 3, l7 = lane & 7;
    int arow = wm + (quad & 1) * 8 + l7;
    int acolb = (quad >> 1) * 16;
    int brow = wn + (quad >> 1) * 8 + l7;
    int bcolb = (quad & 1) * 16;

    stage(0, 0);
    if (nch > 1) stage(1, 1);

    for (int c = 0; c < nch; c++) {
        int buf = c % 3;
        if (c + 2 < nch) { stage(c + 2, (c + 2) % 3); CP_WAIT(2); }
        else if (c + 1 < nch) { CP_WAIT(1); }
        else { CP_WAIT(0); }
        __syncthreads();

        u32 baseA = sb + buf * BUFB;
        u32 baseW = baseA + 32768;
#pragma unroll
        for (int ks = 0; ks < 4; ks++) {
            u32 ah[2][4], al[2][4];
#pragma unroll
            for (int mt = 0; mt < 2; mt++) {
                u32 off = SW128((arow + mt * 16) * 128 + acolb + ks * 32);
                ldsm4(ah[mt], baseA + off);
                ldsm4(al[mt], baseA + 16384 + off);
            }
#pragma unroll
            for (int nt2 = 0; nt2 < 4; nt2++) {
                u32 off = SW128((brow + nt2 * 16) * 128 + bcolb + ks * 32);
                u32 bh[4], bl[4];
                ldsm4(bh, baseW + off);
                ldsm4(bl, baseW + 16384 + off);
#pragma unroll
                for (int mt = 0; mt < 2; mt++) {
                    mma_f16(acc[mt][2 * nt2],     ah[mt], bh);
                    mma_f16(acc[mt][2 * nt2],     ah[mt], bl);
                    mma_f16(acc[mt][2 * nt2],     al[mt], bh);
                    mma_f16(acc[mt][2 * nt2 + 1], ah[mt], bh + 2);
                    mma_f16(acc[mt][2 * nt2 + 1], ah[mt], bl + 2);
                    mma_f16(acc[mt][2 * nt2 + 1], al[mt], bh + 2);
                }
            }
        }
        __syncthreads();
    }

    if (tid < 128) {
        int co = co0 + tid;
        s_bias[tid] = (co < CO) ? bias[co] : 0.f;
    }
    __syncthreads();

    int g = lane >> 2, tg = lane & 3;
    float ssum = 0.f, ssq = 0.f;
#pragma unroll
    for (int mt = 0; mt < 2; mt++) {
#pragma unroll
        for (int nt = 0; nt < 8; nt++) {
            int colb = wn + nt * 8 + tg * 2;
            float b0 = s_bias[colb], b1 = s_bias[colb + 1];
            float f00 = acc[mt][nt][0] + b0, f01 = acc[mt][nt][1] + b1;
            float f10 = acc[mt][nt][2] + b0, f11 = acc[mt][nt][3] + b1;
            int m1 = m0 + wm + mt * 16 + g;
            int co = co0 + colb;
            if (MODE == 0) {
                float* y0 = &Y[(size_t)m1 * CO + co];
                float* y1 = &Y[(size_t)(m1 + 8) * CO + co];
                if (accum) {
                    float2 o0v = *(float2*)y0, o1v = *(float2*)y1;
                    f00 += o0v.x; f01 += o0v.y; f10 += o1v.x; f11 += o1v.y;
                }
                *(float2*)y0 = make_float2(f00, f01);
                *(float2*)y1 = make_float2(f10, f11);
                ssum += f00 + f01 + f10 + f11;
                ssq += f00 * f00 + f01 * f01 + f10 * f10 + f11 * f11;
            } else {
                int b = m1 >> 11, t = m1 & 2047;
                if (co < CO) {
                    float* p0 = &Y[((size_t)b * CO + co) * TLEN + t];
                    if (accum) { f00 += p0[0]; f10 += p0[8]; }
                    p0[0] = f00; p0[8] = f10;
                    ssum += f00 + f10; ssq += f00 * f00 + f10 * f10;
                }
                if (co + 1 < CO) {
                    float* p1 = &Y[((size_t)b * CO + co + 1) * TLEN + t];
                    if (accum) { f01 += p1[0]; f11 += p1[8]; }
                    p1[0] = f01; p1[8] = f11;
                    ssum += f01 + f11; ssq += f01 * f01 + f11 * f11;
                }
            }
        }
    }

    if (doStats) {
#pragma unroll
        for (int off = 16; off > 0; off >>= 1) {
            ssum += __shfl_down_sync(0xffffffffu, ssum, off);
            ssq  += __shfl_down_sync(0xffffffffu, ssq,  off);
        }
        if (lane == 0) { s_red[wid] = ssum; s_red[8 + wid] = ssq; }
        __syncthreads();
        if (tid == 0) {
            double s = 0.0, s2 = 0.0;
            for (int w = 0; w < 8; w++) { s += s_red[w]; s2 += s_red[8 + w]; }
            int b = m0 >> 11;
            atomicAdd(&g_stats[2 * b], s);
            atomicAdd(&g_stats[2 * b + 1], s2);
        }
    }
}

__global__ void gn_glu_split2(const float* __restrict__ X,
                              const float* __restrict__ g,
                              const float* __restrict__ bt,
                              u16* __restrict__ catH, u16* __restrict__ catL) {
    int m = blockIdx.y;
    int c = blockIdx.x * 256 + threadIdx.x;
    int b = m >> 11;
    double N = 1024.0 * TLEN;
    double mean = g_stats[2 * b] / N;
    double var  = g_stats[2 * b + 1] / N - mean * mean;
    float rstd = (float)rsqrt(var + GN_EPS);
    float mf = (float)mean;
    float a  = X[(size_t)m * 1024 + c];
    float gv = X[(size_t)m * 1024 + 512 + c];
    float na = (a  - mf) * rstd * g[c]       + bt[c];
    float ng = (gv - mf) * rstd * g[c + 512] + bt[c + 512];
    float v = na / (1.f + expf(-ng));
    split2h(v, catH, catL, (size_t)m * 640 + 128 + c);
}

// ---------------- host ----------------
static const int SMEM_K5 = (2 * (8 * 132) + 2 * (8 * 5 * 128) + 16) * 4;
static const int SMEM_G  = 3 * 4 * 16384;

extern "C" void kernel_launch(void* const* d_in, const int* in_sizes, int n_in,
                              void* d_out, int out_size) {
    const float* x    = (const float*)d_in[0];
    const int*   y    = (const int*)  d_in[1];
    const float* spk  = (const float*)d_in[2];
    const float* cb   = (const float*)d_in[3];
    const float *ew0 = (const float*)d_in[4],  *eb0 = (const float*)d_in[5];
    const float *eg0 = (const float*)d_in[6],  *et0 = (const float*)d_in[7];
    const float *ew1 = (const float*)d_in[8],  *eb1 = (const float*)d_in[9];
    const float *eg1 = (const float*)d_in[10], *et1 = (const float*)d_in[11];
    const float *ew2 = (const float*)d_in[12], *eb2 = (const float*)d_in[13];
    const float *eg2 = (const float*)d_in[14], *et2 = (const float*)d_in[15];
    const float *mw  = (const float*)d_in[16], *mb  = (const float*)d_in[17];
    const float *dw0 = (const float*)d_in[18], *db0 = (const float*)d_in[19];
    const float *dg0 = (const float*)d_in[20], *dt0 = (const float*)d_in[21];
    const float *dw1 = (const float*)d_in[22], *db1 = (const float*)d_in[23];
    const float *dg1 = (const float*)d_in[24], *dt1 = (const float*)d_in[25];
    const float *dw2 = (const float*)d_in[26], *db2 = (const float*)d_in[27];
    float* out = (float*)d_out;

    cudaFuncSetAttribute(conv_f2_kernel<5>,
                         cudaFuncAttributeMaxDynamicSharedMemorySize, SMEM_K5);
    cudaFuncSetAttribute(gemm_mma_kernel<0>,
                         cudaFuncAttributeMaxDynamicSharedMemorySize, SMEM_G);
    cudaFuncSetAttribute(gemm_mma_kernel<2>,
                         cudaFuncAttributeMaxDynamicSharedMemorySize, SMEM_G);

    float *bufA, *z, *spkn, *cbn, *we0, *zbias;
    u16 *aH, *aL, *a2H, *a2L, *bH, *bL, *catH, *catL;
    u16 *w1ah, *w1al, *w1bh, *w1bl, *w2h, *w2l, *wmh, *wml;
    u16 *d0h, *d0l, *d1h, *d1l, *d2h, *d2l;
    cudaGetSymbolAddress((void**)&bufA, g_bufA);
    cudaGetSymbolAddress((void**)&z,    g_z);
    cudaGetSymbolAddress((void**)&spkn, g_spkn);
    cudaGetSymbolAddress((void**)&cbn,  g_cbn);
    cudaGetSymbolAddress((void**)&we0,  g_we0);
    cudaGetSymbolAddress((void**)&zbias, g_zbias);
    cudaGetSymbolAddress((void**)&aH,  g_aH);  cudaGetSymbolAddress((void**)&aL,  g_aL);
    cudaGetSymbolAddress((void**)&a2H, g_a2H); cudaGetSymbolAddress((void**)&a2L, g_a2L);
    cudaGetSymbolAddress((void**)&bH,  g_bH);  cudaGetSymbolAddress((void**)&bL,  g_bL);
    cudaGetSymbolAddress((void**)&catH, g_catH);
    cudaGetSymbolAddress((void**)&catL, g_catL);
    cudaGetSymbolAddress((void**)&w1ah, g_w1ah); cudaGetSymbolAddress((void**)&w1al, g_w1al);
    cudaGetSymbolAddress((void**)&w1bh, g_w1bh); cudaGetSymbolAddress((void**)&w1bl, g_w1bl);
    cudaGetSymbolAddress((void**)&w2h, g_w2h); cudaGetSymbolAddress((void**)&w2l, g_w2l);
    cudaGetSymbolAddress((void**)&wmh, g_wmh); cudaGetSymbolAddress((void**)&wml, g_wml);
    cudaGetSymbolAddress((void**)&d0h, g_d0h); cudaGetSymbolAddress((void**)&d0l, g_d0l);
    cudaGetSymbolAddress((void**)&d1h, g_d1h); cudaGetSymbolAddress((void**)&d1l, g_d1l);
    cudaGetSymbolAddress((void**)&d2h, g_d2h); cudaGetSymbolAddress((void**)&d2l, g_d2l);

    // ---- prep ----
    normalize_rows_kernel<<<64, 128>>>(spk, spkn);
    normalize_rows_kernel<<<512, 128>>>(cb, cbn);
    zero_bias_kernel<<<4, 256>>>();
    gather_yv_kernel<<<MTOT, 128>>>(y, spkn, catH, catL);
    wenc_kernel<<<(1024 * 39 * 5 + 255) / 256, 256>>>(ew0, we0, 39, 1024, 5);
    wsplit_enc_h<<<(512 * 2560 + 255) / 256, 256>>>(ew1, w1ah, w1al, 1024, 512, 512, 5, 0);
    wsplit_enc_h<<<(512 * 2560 + 255) / 256, 256>>>(ew1, w1bh, w1bl, 1024, 512, 512, 5, 512);
    wsplit_enc_h<<<(512 * 2560 + 255) / 256, 256>>>(ew2, w2h, w2l, 512, 512, 512, 5, 0);
    wsplit_enc_h<<<(128 * 512 + 255) / 256, 256>>>(mw, wmh, wml, 512, 512, 128, 1, 0);
    wsplit_dec<<<(1024 * 1280 + 255) / 256, 256>>>(dw0, d0h, d0l, 256, 1024, 128);
    wsplit_dec<<<(1024 * 3200 + 255) / 256, 256>>>(dw1, d1h, d1l, 640, 1024, 512);
    wsplit_dec<<<(39 * 3200 + 255) / 256, 256>>>(dw2, d2h, d2l, 640, 39, 512);

    // ---- enc L0 (FFMA2) + GN + dual transpose->split halves ----
    zero_stats_kernel<<<1, 32>>>();
    conv_f2_kernel<5><<<dim3(TLEN / 128, 8, BATCH), 256, SMEM_K5>>>(
        x, we0, eb0, bufA, 39, 39, 1024, 1);
    gn_lrelu_t_split2<<<dim3(TLEN / 32, 16, BATCH), dim3(32, 8)>>>(
        bufA, eg0, et0, 1024, 0, 512, aH, aL);
    gn_lrelu_t_split2<<<dim3(TLEN / 32, 16, BATCH), dim3(32, 8)>>>(
        bufA, eg0, et0, 1024, 512, 512, a2H, a2L);

    // ---- enc L1 = two CS=512 gemms with accumulation ----
    zero_stats_kernel<<<1, 32>>>();
    gemm_mma_kernel<0><<<dim3(4, MTOT / 128), 256, SMEM_G>>>(
        aH, aL, w1ah, w1al, eb1, bufA, 512, 512, 5, 512, 0, 0);
    gemm_mma_kernel<0><<<dim3(4, MTOT / 128), 256, SMEM_G>>>(
        a2H, a2L, w1bh, w1bl, zbias, bufA, 512, 512, 5, 512, 1, 1);
    gn_lrelu_split2<<<dim3(2, MTOT), 256>>>(bufA, eg1, et1, 512, bH, bL);

    // ---- enc L2 (proven CS=512 gemm) ----
    zero_stats_kernel<<<1, 32>>>();
    gemm_mma_kernel<0><<<dim3(4, MTOT / 128), 256, SMEM_G>>>(
        bH, bL, w2h, w2l, eb2, bufA, 512, 512, 5, 512, 1, 0);
    gn_lrelu_split2<<<dim3(2, MTOT), 256>>>(bufA, eg2, et2, 512, aH, aL);

    // ---- 1x1 (proven gemm K=1 MODE2 -> z) ----
    gemm_mma_kernel<2><<<dim3(1, MTOT / 128), 256, SMEM_G>>>(
        aH, aL, wmh, wml, mb, z, 512, 512, 1, 128, 0, 0);

    // ---- VQ -> cat ----
    vq_kernel<<<MTOT / 8, 256>>>(z, cbn, catH, catL);

    // ---- decoder (proven) ----
    zero_stats_kernel<<<1, 32>>>();
    gemm_mma_kernel<0><<<dim3(8, MTOT / 128), 256, SMEM_G>>>(
        catH, catL, d0h, d0l, db0, bufA, 640, 256, 5, 1024, 1, 0);
    gn_glu_split2<<<dim3(2, MTOT), 256>>>(bufA, dg0, dt0, catH, catL);

    zero_stats_kernel<<<1, 32>>>();
    gemm_mma_kernel<0><<<dim3(8, MTOT / 128), 256, SMEM_G>>>(
        catH, catL, d1h, d1l, db1, bufA, 640, 640, 5, 1024, 1, 0);
    gn_glu_split2<<<dim3(2, MTOT), 256>>>(bufA, dg1, dt1, catH, catL);

    gemm_mma_kernel<2><<<dim3(1, MTOT / 128), 256, SMEM_G>>>(
        catH, catL, d2h, d2l, db2, out, 640, 640, 5, 39, 0, 0);
}